// round 1
// baseline (speedup 1.0000x reference)
#include <cuda_runtime.h>
#include <math.h>

#define D 128
#define NF_MAX 50000

// scratch (static device globals; no allocation in kernel_launch)
__device__ float g_xw[(size_t)NF_MAX * D];
__device__ float g_acc[(size_t)NF_MAX * D];
__device__ float g_xf[(size_t)NF_MAX * D];
__device__ float g_deg[NF_MAX];
__device__ float g_dinv[NF_MAX];

// ---------------- degree / dinv ----------------
__global__ void k_degree(const int* __restrict__ dst, int E, float* __restrict__ deg) {
    int e = blockIdx.x * blockDim.x + threadIdx.x;
    if (e < E) atomicAdd(&deg[dst[e]], 1.0f);
}

__global__ void k_dinv(const float* __restrict__ deg, float* __restrict__ dinv, int n) {
    int i = blockIdx.x * blockDim.x + threadIdx.x;
    if (i < n) dinv[i] = rsqrtf(deg[i] + 1.0f);   // +1 self loop
}

// ---------------- SGEMM: C[n,128] = A[n,128] @ W[128,128] ----------------
// 128 threads/block, each block computes 16 rows x 128 cols.
__global__ void k_gemm128(const float* __restrict__ A, const float* __restrict__ W,
                          float* __restrict__ C, int n) {
    __shared__ float Ws[32][D];   // k-tile x cols
    __shared__ float As[16][32];  // rows x k-tile
    const int c = threadIdx.x;          // output column
    const int row0 = blockIdx.x * 16;
    float acc[16];
#pragma unroll
    for (int r = 0; r < 16; r++) acc[r] = 0.f;

    for (int kt = 0; kt < D; kt += 32) {
#pragma unroll
        for (int i = 0; i < 32; i++) Ws[i][c] = W[(size_t)(kt + i) * D + c];
        for (int i = threadIdx.x; i < 16 * 32; i += 128) {
            int r = i >> 5, k = i & 31;
            int row = row0 + r;
            As[r][k] = (row < n) ? A[(size_t)row * D + kt + k] : 0.f;
        }
        __syncthreads();
#pragma unroll
        for (int k = 0; k < 32; k++) {
            float w = Ws[k][c];
#pragma unroll
            for (int r = 0; r < 16; r++) acc[r] += As[r][k] * w;
        }
        __syncthreads();
    }
#pragma unroll
    for (int r = 0; r < 16; r++) {
        int row = row0 + r;
        if (row < n) C[(size_t)row * D + c] = acc[r];
    }
}

// ---------------- edge scatter: one warp per edge ----------------
__global__ void k_edge(const int* __restrict__ src, const int* __restrict__ dst,
                       const float* __restrict__ dinv, const float* __restrict__ xw,
                       float* __restrict__ acc, int E) {
    int w = (blockIdx.x * blockDim.x + threadIdx.x) >> 5;
    int lane = threadIdx.x & 31;
    if (w >= E) return;
    int s = src[w], d = dst[w];
    float nw = dinv[s] * dinv[d];
    float4 v = reinterpret_cast<const float4*>(xw + (size_t)s * D)[lane];
    float* o = acc + (size_t)d * D + lane * 4;
    atomicAdd(o + 0, v.x * nw);
    atomicAdd(o + 1, v.y * nw);
    atomicAdd(o + 2, v.z * nw);
    atomicAdd(o + 3, v.w * nw);
}

// ---------------- finalize: self-loop + bias + ELU (+ optional unpool scatter) ----------------
__global__ void k_final(const float* __restrict__ acc, const float* __restrict__ xw,
                        const float* __restrict__ dinv, const float* __restrict__ b,
                        const int* __restrict__ unpool, float* __restrict__ out, int n) {
    int idx = blockIdx.x * blockDim.x + threadIdx.x;
    if (idx >= n * D) return;
    int row = idx >> 7;
    int f = idx & (D - 1);
    float di = dinv[row];
    float v = acc[idx] + xw[idx] * di * di + b[f];
    v = v > 0.f ? v : expm1f(v);
    int orow = unpool ? unpool[row] : row;
    out[(size_t)orow * D + f] = v;
}

static inline int cdiv(int a, int b) { return (a + b - 1) / b; }

extern "C" void kernel_launch(void* const* d_in, const int* in_sizes, int n_in,
                              void* d_out, int out_size) {
    // inputs: x, edge_index, pooled_x, pooled_edge_index, unpool_info,
    //         W0, b0, W1, b1, W2, b2
    const int*   ei     = (const int*)d_in[1];
    const float* px     = (const float*)d_in[2];
    const int*   pei    = (const int*)d_in[3];
    const int*   unpool = (const int*)d_in[4];
    const float* W0 = (const float*)d_in[5];
    const float* b0 = (const float*)d_in[6];
    const float* W1 = (const float*)d_in[7];
    const float* b1 = (const float*)d_in[8];
    const float* W2 = (const float*)d_in[9];
    const float* b2 = (const float*)d_in[10];

    const int nf = in_sizes[0] / D;   // 50000
    const int Ef = in_sizes[1] / 2;   // 600000
    const int np = in_sizes[2] / D;   // 12500
    const int Ep = in_sizes[3] / 2;   // 150000
    float* out = (float*)d_out;

    float *xw, *acc, *xf, *deg, *dinv;
    cudaGetSymbolAddress((void**)&xw,   g_xw);
    cudaGetSymbolAddress((void**)&acc,  g_acc);
    cudaGetSymbolAddress((void**)&xf,   g_xf);
    cudaGetSymbolAddress((void**)&deg,  g_deg);
    cudaGetSymbolAddress((void**)&dinv, g_dinv);

    // ===== conv0 on pooled graph =====
    cudaMemsetAsync(deg, 0, (size_t)np * sizeof(float));
    k_degree<<<cdiv(Ep, 256), 256>>>(pei + Ep, Ep, deg);
    k_dinv<<<cdiv(np, 256), 256>>>(deg, dinv, np);
    k_gemm128<<<cdiv(np, 16), 128>>>(px, W0, xw, np);
    cudaMemsetAsync(acc, 0, (size_t)np * D * sizeof(float));
    k_edge<<<cdiv(Ep, 8), 256>>>(pei, pei + Ep, dinv, xw, acc, Ep);
    // unpool: zero full-size xf, scatter ELU'd rows to kept indices
    cudaMemsetAsync(xf, 0, (size_t)nf * D * sizeof(float));
    k_final<<<cdiv(np * D, 256), 256>>>(acc, xw, dinv, b0, unpool, xf, np);

    // ===== conv1 on full graph =====
    cudaMemsetAsync(deg, 0, (size_t)nf * sizeof(float));
    k_degree<<<cdiv(Ef, 256), 256>>>(ei + Ef, Ef, deg);
    k_dinv<<<cdiv(nf, 256), 256>>>(deg, dinv, nf);
    k_gemm128<<<cdiv(nf, 16), 128>>>(xf, W1, xw, nf);
    cudaMemsetAsync(acc, 0, (size_t)nf * D * sizeof(float));
    k_edge<<<cdiv(Ef, 8), 256>>>(ei, ei + Ef, dinv, xw, acc, Ef);
    k_final<<<cdiv(nf * D, 256), 256>>>(acc, xw, dinv, b1, nullptr, xf, nf);

    // ===== conv2 on full graph (same degrees) =====
    k_gemm128<<<cdiv(nf, 16), 128>>>(xf, W2, xw, nf);
    cudaMemsetAsync(acc, 0, (size_t)nf * D * sizeof(float));
    k_edge<<<cdiv(Ef, 8), 256>>>(ei, ei + Ef, dinv, xw, acc, Ef);
    k_final<<<cdiv(nf * D, 256), 256>>>(acc, xw, dinv, b2, nullptr, out, nf);
}

// round 2
// speedup vs baseline: 2.1263x; 2.1263x over previous
#include <cuda_runtime.h>
#include <math.h>

#define D 128
#define NF_MAX 50000
#define EF_MAX 600000

// scratch (static device globals)
__device__ float g_buf1[(size_t)NF_MAX * D];
__device__ float g_buf2[(size_t)NF_MAX * D];
__device__ float g_buf3[(size_t)NF_MAX * D];
__device__ int   g_cnt[NF_MAX];
__device__ int   g_rp[NF_MAX + 1];
__device__ int   g_cur[NF_MAX];
__device__ int   g_esrc[EF_MAX];
__device__ float g_dinv[NF_MAX];
__device__ unsigned char g_nz[NF_MAX];

static inline int cdiv(int a, int b) { return (a + b - 1) / b; }

// ---------------- CSR build ----------------
__global__ void k_hist(const int* __restrict__ dst, int E, int* __restrict__ cnt) {
    int e = blockIdx.x * blockDim.x + threadIdx.x;
    if (e < E) atomicAdd(&cnt[dst[e]], 1);
}

// single-block exclusive scan over n counts -> rp[0..n]
__global__ void k_scan(const int* __restrict__ cnt, int* __restrict__ rp, int n) {
    __shared__ int ssum[1024];
    int t = threadIdx.x;
    int C = (n + 1023) / 1024;
    int lo = t * C, hi = min(lo + C, n);
    int s = 0;
    for (int i = lo; i < hi; i++) s += cnt[i];
    ssum[t] = s;
    __syncthreads();
    for (int off = 1; off < 1024; off <<= 1) {
        int v = 0;
        if (t >= off) v = ssum[t - off];
        __syncthreads();
        if (t >= off) ssum[t] += v;
        __syncthreads();
    }
    int pre = (t == 0) ? 0 : ssum[t - 1];
    for (int i = lo; i < hi; i++) { rp[i] = pre; pre += cnt[i]; }
    if (t == 1023) rp[n] = ssum[1023];
}

__global__ void k_dinv(const int* __restrict__ cnt, float* __restrict__ dinv, int n) {
    int i = blockIdx.x * blockDim.x + threadIdx.x;
    if (i < n) dinv[i] = rsqrtf((float)cnt[i] + 1.0f);  // +1 self loop
}

__global__ void k_place(const int* __restrict__ src, const int* __restrict__ dst, int E,
                        int* __restrict__ cur, int* __restrict__ esrc) {
    int e = blockIdx.x * blockDim.x + threadIdx.x;
    if (e >= E) return;
    int p = atomicAdd(&cur[dst[e]], 1);
    esrc[p] = src[e];
}

// ---------------- SGEMM: C[n,128] = A[n,128] @ W[128,128] ----------------
// block = 128 threads, computes 64 rows x 128 cols. Dynamic smem: W (64KB) + A tile (32KB).
__global__ void k_gemm(const float* __restrict__ A, const float* __restrict__ W,
                       float* __restrict__ C, int n) {
    extern __shared__ float sm[];
    float* Ws = sm;            // [k][c] 128*128
    float* As = sm + D * D;    // [r][k] 64*128
    const int tid = threadIdx.x;
    const int row0 = blockIdx.x * 64;

    for (int i = tid; i < D * D / 4; i += 128)
        reinterpret_cast<float4*>(Ws)[i] = reinterpret_cast<const float4*>(W)[i];
    for (int i = tid; i < 64 * D / 4; i += 128) {
        int r = i >> 5;               // D/4 = 32 float4 per row
        int row = row0 + r;
        reinterpret_cast<float4*>(As)[i] =
            (row < n) ? reinterpret_cast<const float4*>(A)[(size_t)row * 32 + (i & 31)]
                      : make_float4(0.f, 0.f, 0.f, 0.f);
    }
    __syncthreads();

    const int cg = tid & 31;   // col group: cols 4*cg..4*cg+3
    const int rg = tid >> 5;   // row group: rows rg*16..rg*16+15
    float4 acc[16];
#pragma unroll
    for (int r = 0; r < 16; r++) acc[r] = make_float4(0.f, 0.f, 0.f, 0.f);

#pragma unroll 4
    for (int k = 0; k < D; k++) {
        float4 wv = reinterpret_cast<const float4*>(Ws + k * D)[cg];
#pragma unroll
        for (int r = 0; r < 16; r++) {
            float a = As[(rg * 16 + r) * D + k];
            acc[r].x += a * wv.x; acc[r].y += a * wv.y;
            acc[r].z += a * wv.z; acc[r].w += a * wv.w;
        }
    }
#pragma unroll
    for (int r = 0; r < 16; r++) {
        int row = row0 + rg * 16 + r;
        if (row < n)
            reinterpret_cast<float4*>(C)[(size_t)row * 32 + cg] = acc[r];
    }
}

// ---------------- CSR gather: warp per dst row, fused norm + self-loop + bias + ELU ----------------
__global__ void k_gather(const int* __restrict__ rp, const int* __restrict__ esrc,
                         const float* __restrict__ dinv, const float* __restrict__ xw,
                         const float* __restrict__ bias, const unsigned char* __restrict__ nz,
                         float* __restrict__ out, int n) {
    int row = blockIdx.x * (blockDim.x >> 5) + (threadIdx.x >> 5);
    if (row >= n) return;
    int lane = threadIdx.x & 31;
    float di = dinv[row];
    float4 acc = make_float4(0.f, 0.f, 0.f, 0.f);
    // self loop
    if (!nz || nz[row]) {
        float4 v = reinterpret_cast<const float4*>(xw + (size_t)row * D)[lane];
        float w = di * di;
        acc.x = v.x * w; acc.y = v.y * w; acc.z = v.z * w; acc.w = v.w * w;
    }
    int s0 = rp[row], s1 = rp[row + 1];
    for (int base = s0; base < s1; base += 32) {
        int cnt = min(32, s1 - base);
        int sid = 0; float dv = 0.f; int fl = 1;
        if (lane < cnt) {
            sid = esrc[base + lane];
            dv = dinv[sid];
            if (nz) fl = nz[sid];
        }
        for (int j = 0; j < cnt; j++) {
            int s   = __shfl_sync(0xffffffffu, sid, j);
            int f   = __shfl_sync(0xffffffffu, fl, j);
            float w = __shfl_sync(0xffffffffu, dv, j) * di;
            if (!f) continue;
            float4 v = reinterpret_cast<const float4*>(xw + (size_t)s * D)[lane];
            acc.x += v.x * w; acc.y += v.y * w; acc.z += v.z * w; acc.w += v.w * w;
        }
    }
    float4 bb = reinterpret_cast<const float4*>(bias)[lane];
    acc.x += bb.x; acc.y += bb.y; acc.z += bb.z; acc.w += bb.w;
    acc.x = acc.x > 0.f ? acc.x : expm1f(acc.x);
    acc.y = acc.y > 0.f ? acc.y : expm1f(acc.y);
    acc.z = acc.z > 0.f ? acc.z : expm1f(acc.z);
    acc.w = acc.w > 0.f ? acc.w : expm1f(acc.w);
    reinterpret_cast<float4*>(out)[(size_t)row * 32 + lane] = acc;
}

// ---------------- unpool scatter of GEMM'd pooled rows into full table + nz flags ----------------
__global__ void k_scatter(const float* __restrict__ hw, const int* __restrict__ unpool,
                          float* __restrict__ xwf, unsigned char* __restrict__ nz, int np) {
    int idx = blockIdx.x * blockDim.x + threadIdx.x;
    if (idx >= np * 32) return;
    int r = idx >> 5, q = idx & 31;
    int orow = unpool[r];
    reinterpret_cast<float4*>(xwf)[(size_t)orow * 32 + q] =
        reinterpret_cast<const float4*>(hw)[(size_t)r * 32 + q];
    if (q == 0) nz[orow] = 1;
}

extern "C" void kernel_launch(void* const* d_in, const int* in_sizes, int n_in,
                              void* d_out, int out_size) {
    const int*   ei     = (const int*)d_in[1];
    const float* px     = (const float*)d_in[2];
    const int*   pei    = (const int*)d_in[3];
    const int*   unpool = (const int*)d_in[4];
    const float* W0 = (const float*)d_in[5];
    const float* b0 = (const float*)d_in[6];
    const float* W1 = (const float*)d_in[7];
    const float* b1 = (const float*)d_in[8];
    const float* W2 = (const float*)d_in[9];
    const float* b2 = (const float*)d_in[10];

    const int nf = in_sizes[0] / D;   // 50000
    const int Ef = in_sizes[1] / 2;   // 600000
    const int np = in_sizes[2] / D;   // 12500
    const int Ep = in_sizes[3] / 2;   // 150000
    float* out = (float*)d_out;

    float *buf1, *buf2, *buf3, *dinv;
    int *cnt, *rp, *cur, *esrc;
    unsigned char* nz;
    cudaGetSymbolAddress((void**)&buf1, g_buf1);
    cudaGetSymbolAddress((void**)&buf2, g_buf2);
    cudaGetSymbolAddress((void**)&buf3, g_buf3);
    cudaGetSymbolAddress((void**)&cnt,  g_cnt);
    cudaGetSymbolAddress((void**)&rp,   g_rp);
    cudaGetSymbolAddress((void**)&cur,  g_cur);
    cudaGetSymbolAddress((void**)&esrc, g_esrc);
    cudaGetSymbolAddress((void**)&dinv, g_dinv);
    cudaGetSymbolAddress((void**)&nz,   g_nz);

    cudaFuncSetAttribute(k_gemm, cudaFuncAttributeMaxDynamicSharedMemorySize,
                         (D * D + 64 * D) * (int)sizeof(float));
    const int GEMM_SMEM = (D * D + 64 * D) * (int)sizeof(float);

    // ===== pooled CSR + dinv =====
    cudaMemsetAsync(cnt, 0, (size_t)np * sizeof(int));
    k_hist<<<cdiv(Ep, 256), 256>>>(pei + Ep, Ep, cnt);
    k_scan<<<1, 1024>>>(cnt, rp, np);
    k_dinv<<<cdiv(np, 256), 256>>>(cnt, dinv, np);
    cudaMemcpyAsync(cur, rp, (size_t)np * sizeof(int), cudaMemcpyDeviceToDevice);
    k_place<<<cdiv(Ep, 256), 256>>>(pei, pei + Ep, Ep, cur, esrc);

    // ===== conv0 on pooled graph: h = ELU(gcn(px,W0,b0)) compact in buf2 =====
    k_gemm<<<cdiv(np, 64), 128, GEMM_SMEM>>>(px, W0, buf1, np);
    k_gather<<<cdiv(np, 8), 256>>>(rp, esrc, dinv, buf1, b0, nullptr, buf2, np);

    // ===== full CSR + dinv (reused by conv1 and conv2) =====
    cudaMemsetAsync(cnt, 0, (size_t)nf * sizeof(int));
    k_hist<<<cdiv(Ef, 256), 256>>>(ei + Ef, Ef, cnt);
    k_scan<<<1, 1024>>>(cnt, rp, nf);
    k_dinv<<<cdiv(nf, 256), 256>>>(cnt, dinv, nf);
    cudaMemcpyAsync(cur, rp, (size_t)nf * sizeof(int), cudaMemcpyDeviceToDevice);
    k_place<<<cdiv(Ef, 256), 256>>>(ei, ei + Ef, Ef, cur, esrc);

    // ===== conv1: GEMM only on the np nonzero rows, scatter, sparse gather =====
    k_gemm<<<cdiv(np, 64), 128, GEMM_SMEM>>>(buf2, W1, buf1, np);   // hw [np,128]
    cudaMemsetAsync(buf3, 0, (size_t)nf * D * sizeof(float));
    cudaMemsetAsync(nz, 0, (size_t)nf);
    k_scatter<<<cdiv(np * 32, 256), 256>>>(buf1, unpool, buf3, nz, np);
    k_gather<<<cdiv(nf, 8), 256>>>(rp, esrc, dinv, buf3, b1, nz, buf2, nf);  // xf1 in buf2

    // ===== conv2: full GEMM + gather -> out =====
    k_gemm<<<cdiv(nf, 64), 128, GEMM_SMEM>>>(buf2, W2, buf1, nf);
    k_gather<<<cdiv(nf, 8), 256>>>(rp, esrc, dinv, buf1, b2, nullptr, out, nf);
}

// round 4
// speedup vs baseline: 2.3143x; 1.0884x over previous
#include <cuda_runtime.h>
#include <cuda_bf16.h>
#include <math.h>
#include <stdint.h>

#define D 128
#define NF_MAX 50000
#define NP_MAX 12500
#define EF_MAX 600000

// ---------------- scratch (static device globals) ----------------
__device__ float g_buf1[(size_t)NF_MAX * D];
__device__ float g_buf2[(size_t)NF_MAX * D];
__device__ float g_buf3[(size_t)NF_MAX * D];
__device__ int   g_cntf[NF_MAX];
__device__ int   g_rpf[NF_MAX + 1];
__device__ int   g_curf[NF_MAX];
__device__ int   g_esrcf[EF_MAX];
__device__ float g_dinvf[NF_MAX];
__device__ int   g_cntp[NP_MAX];
__device__ int   g_rpp[NP_MAX + 1];
__device__ int   g_curp[NP_MAX];
__device__ int   g_esrcp[EF_MAX / 4];
__device__ float g_dinvp[NP_MAX];
__device__ unsigned char g_nz[NF_MAX];
// pre-transposed, split, swizzled bf16 W images: [matrix][hi/lo][32KB]
__device__ unsigned char g_wimg[3][2][32768];

static inline int cdiv(int a, int b) { return (a + b - 1) / b; }

// swizzled byte offset inside a [128 rows x 128 k] bf16 tile, row stride 256B.
// XOR of byte bits [4:6] with (row & 7) -> conflict-free ldmatrix.
__host__ __device__ __forceinline__ uint32_t swz(int row, int kbyte) {
    return (uint32_t)(row * 256 + (kbyte ^ ((row & 7) << 4)));
}

__device__ __forceinline__ uint32_t smem_u32(const void* p) {
    uint32_t a;
    asm("{ .reg .u64 t; cvta.to.shared.u64 t, %1; cvt.u32.u64 %0, t; }" : "=r"(a) : "l"(p));
    return a;
}
__device__ __forceinline__ void ldmx4(uint32_t* r, uint32_t addr) {
    asm volatile("ldmatrix.sync.aligned.m8n8.x4.shared.b16 {%0,%1,%2,%3}, [%4];"
                 : "=r"(r[0]), "=r"(r[1]), "=r"(r[2]), "=r"(r[3]) : "r"(addr));
}
__device__ __forceinline__ void mma16816(float* c, const uint32_t* a, uint32_t b0, uint32_t b1) {
    asm volatile("mma.sync.aligned.m16n8k16.row.col.f32.bf16.bf16.f32 "
                 "{%0,%1,%2,%3}, {%4,%5,%6,%7}, {%8,%9}, {%0,%1,%2,%3};"
                 : "+f"(c[0]), "+f"(c[1]), "+f"(c[2]), "+f"(c[3])
                 : "r"(a[0]), "r"(a[1]), "r"(a[2]), "r"(a[3]), "r"(b0), "r"(b1));
}

// ================= CSR build (both graphs fused) =================
__global__ void k_zero(int* cntf, int* cntp, unsigned char* nz, int nf, int np) {
    int i = blockIdx.x * blockDim.x + threadIdx.x;
    if (i < nf) { cntf[i] = 0; nz[i] = 0; }
    if (i < np) cntp[i] = 0;
}

__global__ void k_hist2(const int* __restrict__ dstf, int Ef, int* __restrict__ cntf,
                        const int* __restrict__ dstp, int Ep, int* __restrict__ cntp) {
    int e = blockIdx.x * blockDim.x + threadIdx.x;
    if (e < Ef) atomicAdd(&cntf[dstf[e]], 1);
    else if (e < Ef + Ep) atomicAdd(&cntp[dstp[e - Ef]], 1);
}

__global__ void k_scan2(const int* __restrict__ cntf, int* rpf, int* curf, float* dinvf, int nf,
                        const int* __restrict__ cntp, int* rpp, int* curp, float* dinvp, int np) {
    const int* cnt = blockIdx.x ? cntp : cntf;
    int* rp = blockIdx.x ? rpp : rpf;
    int* cur = blockIdx.x ? curp : curf;
    float* dinv = blockIdx.x ? dinvp : dinvf;
    int n = blockIdx.x ? np : nf;
    __shared__ int ssum[1024];
    int t = threadIdx.x;
    int C = (n + 1023) / 1024;
    int lo = t * C, hi = min(lo + C, n);
    int s = 0;
    for (int i = lo; i < hi; i++) s += cnt[i];
    ssum[t] = s;
    __syncthreads();
    for (int off = 1; off < 1024; off <<= 1) {
        int v = 0;
        if (t >= off) v = ssum[t - off];
        __syncthreads();
        if (t >= off) ssum[t] += v;
        __syncthreads();
    }
    int pre = (t == 0) ? 0 : ssum[t - 1];
    for (int i = lo; i < hi; i++) {
        rp[i] = pre; cur[i] = pre;
        dinv[i] = rsqrtf((float)cnt[i] + 1.0f);
        pre += cnt[i];
    }
    if (t == 1023) rp[n] = ssum[1023];
}

__global__ void k_place2(const int* __restrict__ srcf, const int* __restrict__ dstf, int Ef,
                         int* __restrict__ curf, int* __restrict__ esrcf,
                         const int* __restrict__ srcp, const int* __restrict__ dstp, int Ep,
                         int* __restrict__ curp, int* __restrict__ esrcp) {
    int e = blockIdx.x * blockDim.x + threadIdx.x;
    if (e < Ef) {
        int p = atomicAdd(&curf[dstf[e]], 1);
        esrcf[p] = srcf[e];
    } else if (e < Ef + Ep) {
        int i = e - Ef;
        int p = atomicAdd(&curp[dstp[i]], 1);
        esrcp[p] = srcp[i];
    }
}

// ================= W -> transposed, split, swizzled bf16 images =================
// image layout: Wt[n][k] = W[k][n], row = n (256B swizzled rows)
__global__ void k_prepW(const float* __restrict__ W0, const float* __restrict__ W1,
                        const float* __restrict__ W2) {
    int idx = blockIdx.x * blockDim.x + threadIdx.x;
    if (idx >= 3 * 128 * 128) return;
    int w = idx >> 14, rem = idx & 16383;
    int k = rem >> 7, n = rem & 127;
    const float* W = (w == 0) ? W0 : (w == 1) ? W1 : W2;
    float v = W[k * 128 + n];
    __nv_bfloat16 hb = __float2bfloat16(v);
    float r = v - __bfloat162float(hb);
    __nv_bfloat16 lb = __float2bfloat16(r);
    uint32_t sw = swz(n, k * 2);
    *(unsigned short*)(&g_wimg[w][0][sw]) = __bfloat16_as_ushort(hb);
    *(unsigned short*)(&g_wimg[w][1][sw]) = __bfloat16_as_ushort(lb);
}

// ================= tensor-core GEMM via mma.sync bf16-split =================
// 256 threads / CTA, 128 rows x 128 cols per CTA, 16 rows per warp.
__global__ void __launch_bounds__(256, 1) k_gemm_mma(
    const float* __restrict__ A, const unsigned char* __restrict__ Whi,
    const unsigned char* __restrict__ Wlo, float* __restrict__ C, int n) {
    extern __shared__ unsigned char sm[];
    const int OFF_AHI = 0, OFF_ALO = 32768, OFF_BHI = 65536, OFF_BLO = 98304;
    const uint32_t smb = smem_u32(sm);
    const int tid = threadIdx.x, wid = tid >> 5, lane = tid & 31;
    const int row0 = blockIdx.x * 128;

    // copy pre-swizzled W images
    for (int i = tid; i < 2048; i += 256) {
        ((float4*)(sm + OFF_BHI))[i] = ((const float4*)Whi)[i];
        ((float4*)(sm + OFF_BLO))[i] = ((const float4*)Wlo)[i];
    }
    // convert A tile -> bf16 hi/lo, swizzled rows (each thread: half a row)
    {
        int row = tid >> 1, half = tid & 1;
        int gr = row0 + row;
        const float4* Arow = (const float4*)(A + (size_t)gr * D) + half * 16;
        unsigned char* ahi = sm + OFF_AHI;
        unsigned char* alo = sm + OFF_ALO;
#pragma unroll
        for (int q = 0; q < 16; q++) {
            float4 v = (gr < n) ? Arow[q] : make_float4(0.f, 0.f, 0.f, 0.f);
            float f[4] = {v.x, v.y, v.z, v.w};
#pragma unroll
            for (int p = 0; p < 2; p++) {
                float a0 = f[p * 2], a1 = f[p * 2 + 1];
                __nv_bfloat16 h0 = __float2bfloat16(a0), h1 = __float2bfloat16(a1);
                float r0 = a0 - __bfloat162float(h0);
                float r1 = a1 - __bfloat162float(h1);
                __nv_bfloat16 l0 = __float2bfloat16(r0), l1 = __float2bfloat16(r1);
                uint32_t uhi = (uint32_t)__bfloat16_as_ushort(h0) | ((uint32_t)__bfloat16_as_ushort(h1) << 16);
                uint32_t ulo = (uint32_t)__bfloat16_as_ushort(l0) | ((uint32_t)__bfloat16_as_ushort(l1) << 16);
                int k = half * 64 + q * 4 + p * 2;
                uint32_t sw = swz(row, k * 2);
                *(uint32_t*)(ahi + sw) = uhi;
                *(uint32_t*)(alo + sw) = ulo;
            }
        }
    }
    __syncthreads();

    // per-warp MMA: rows m0..m0+15, all 128 cols (16 n8-tiles)
    const int m0 = wid * 16;
    float acc[16][4];
#pragma unroll
    for (int t = 0; t < 16; t++)
#pragma unroll
        for (int q = 0; q < 4; q++) acc[t][q] = 0.f;

    // lane-dependent ldmatrix address components
    const int a_row = m0 + (lane & 15);
    const uint32_t a_base = smb + (uint32_t)(a_row * 256);
    const int a_swrow = (a_row & 7) << 4;
    const int a_kadd = (lane >> 4) * 16;

    const int b_rowoff = (lane & 7) + (lane >> 4) * 8;   // + n0
    const int b_kadd = ((lane >> 3) & 1) * 16;

#pragma unroll 2
    for (int k0 = 0; k0 < 8; k0++) {
        const int kb = k0 * 32;
        uint32_t ahi[4], alo[4];
        uint32_t a_off = (uint32_t)((kb + a_kadd) ^ a_swrow);
        ldmx4(ahi, a_base + OFF_AHI + a_off);
        ldmx4(alo, a_base + OFF_ALO + a_off);
#pragma unroll
        for (int ntp = 0; ntp < 8; ntp++) {
            const int n0 = ntp * 16;
            const int b_row = n0 + b_rowoff;
            uint32_t b_off = (uint32_t)(b_row * 256 + ((kb + b_kadd) ^ ((b_row & 7) << 4)));
            uint32_t bh[4], bl[4];
            ldmx4(bh, smb + OFF_BHI + b_off);
            ldmx4(bl, smb + OFF_BLO + b_off);
            mma16816(acc[2 * ntp],     ahi, bh[0], bh[1]);
            mma16816(acc[2 * ntp + 1], ahi, bh[2], bh[3]);
            mma16816(acc[2 * ntp],     ahi, bl[0], bl[1]);
            mma16816(acc[2 * ntp + 1], ahi, bl[2], bl[3]);
            mma16816(acc[2 * ntp],     alo, bh[0], bh[1]);
            mma16816(acc[2 * ntp + 1], alo, bh[2], bh[3]);
        }
    }

    // epilogue: direct float2 stores (32B sectors per 4-lane group)
    const int r_lo = row0 + m0 + (lane >> 2);
    const int cbase = (lane & 3) * 2;
    if (r_lo < n) {
        float* crow = C + (size_t)r_lo * D;
#pragma unroll
        for (int t = 0; t < 16; t++)
            *(float2*)(crow + t * 8 + cbase) = make_float2(acc[t][0], acc[t][1]);
    }
    const int r_hi = r_lo + 8;
    if (r_hi < n) {
        float* crow = C + (size_t)r_hi * D;
#pragma unroll
        for (int t = 0; t < 16; t++)
            *(float2*)(crow + t * 8 + cbase) = make_float2(acc[t][2], acc[t][3]);
    }
}

// ================= CSR gather (fused norm + self loop + bias + ELU) =================
__global__ void k_gather(const int* __restrict__ rp, const int* __restrict__ esrc,
                         const float* __restrict__ dinv, const float* __restrict__ xw,
                         const float* __restrict__ bias, const unsigned char* __restrict__ nz,
                         float* __restrict__ out, int n) {
    int row = blockIdx.x * (blockDim.x >> 5) + (threadIdx.x >> 5);
    if (row >= n) return;
    int lane = threadIdx.x & 31;
    float di = dinv[row];
    float4 acc = make_float4(0.f, 0.f, 0.f, 0.f);
    if (!nz || nz[row]) {
        float4 v = reinterpret_cast<const float4*>(xw + (size_t)row * D)[lane];
        float w = di * di;
        acc.x = v.x * w; acc.y = v.y * w; acc.z = v.z * w; acc.w = v.w * w;
    }
    int s0 = rp[row], s1 = rp[row + 1];
    for (int base = s0; base < s1; base += 32) {
        int cnt = min(32, s1 - base);
        int sid = 0; float dv = 0.f; int fl = 1;
        if (lane < cnt) {
            sid = esrc[base + lane];
            dv = dinv[sid];
            if (nz) fl = nz[sid];
        }
        for (int j = 0; j < cnt; j++) {
            int s   = __shfl_sync(0xffffffffu, sid, j);
            int f   = __shfl_sync(0xffffffffu, fl, j);
            float w = __shfl_sync(0xffffffffu, dv, j) * di;
            if (!f) continue;
            float4 v = reinterpret_cast<const float4*>(xw + (size_t)s * D)[lane];
            acc.x += v.x * w; acc.y += v.y * w; acc.z += v.z * w; acc.w += v.w * w;
        }
    }
    float4 bb = reinterpret_cast<const float4*>(bias)[lane];
    acc.x += bb.x; acc.y += bb.y; acc.z += bb.z; acc.w += bb.w;
    acc.x = acc.x > 0.f ? acc.x : expm1f(acc.x);
    acc.y = acc.y > 0.f ? acc.y : expm1f(acc.y);
    acc.z = acc.z > 0.f ? acc.z : expm1f(acc.z);
    acc.w = acc.w > 0.f ? acc.w : expm1f(acc.w);
    reinterpret_cast<float4*>(out)[(size_t)row * 32 + lane] = acc;
}

// ================= unpool scatter (sets nz; no full-table memset needed) =================
__global__ void k_scatter(const float* __restrict__ hw, const int* __restrict__ unpool,
                          float* __restrict__ xwf, unsigned char* __restrict__ nz, int np) {
    int idx = blockIdx.x * blockDim.x + threadIdx.x;
    if (idx >= np * 32) return;
    int r = idx >> 5, q = idx & 31;
    int orow = unpool[r];
    reinterpret_cast<float4*>(xwf)[(size_t)orow * 32 + q] =
        reinterpret_cast<const float4*>(hw)[(size_t)r * 32 + q];
    if (q == 0) nz[orow] = 1;
}

extern "C" void kernel_launch(void* const* d_in, const int* in_sizes, int n_in,
                              void* d_out, int out_size) {
    const int*   ei     = (const int*)d_in[1];
    const float* px     = (const float*)d_in[2];
    const int*   pei    = (const int*)d_in[3];
    const int*   unpool = (const int*)d_in[4];
    const float* W0 = (const float*)d_in[5];
    const float* b0 = (const float*)d_in[6];
    const float* W1 = (const float*)d_in[7];
    const float* b1 = (const float*)d_in[8];
    const float* W2 = (const float*)d_in[9];
    const float* b2 = (const float*)d_in[10];

    const int nf = in_sizes[0] / D;
    const int Ef = in_sizes[1] / 2;
    const int np = in_sizes[2] / D;
    const int Ep = in_sizes[3] / 2;
    float* out = (float*)d_out;

    float *buf1, *buf2, *buf3, *dinvf, *dinvp;
    int *cntf, *rpf, *curf, *esrcf, *cntp, *rpp, *curp, *esrcp;
    unsigned char *nz, *wimg;
    cudaGetSymbolAddress((void**)&buf1,  g_buf1);
    cudaGetSymbolAddress((void**)&buf2,  g_buf2);
    cudaGetSymbolAddress((void**)&buf3,  g_buf3);
    cudaGetSymbolAddress((void**)&cntf,  g_cntf);
    cudaGetSymbolAddress((void**)&rpf,   g_rpf);
    cudaGetSymbolAddress((void**)&curf,  g_curf);
    cudaGetSymbolAddress((void**)&esrcf, g_esrcf);
    cudaGetSymbolAddress((void**)&dinvf, g_dinvf);
    cudaGetSymbolAddress((void**)&cntp,  g_cntp);
    cudaGetSymbolAddress((void**)&rpp,   g_rpp);
    cudaGetSymbolAddress((void**)&curp,  g_curp);
    cudaGetSymbolAddress((void**)&esrcp, g_esrcp);
    cudaGetSymbolAddress((void**)&dinvp, g_dinvp);
    cudaGetSymbolAddress((void**)&nz,    g_nz);
    cudaGetSymbolAddress((void**)&wimg,  g_wimg);

    const int GEMM_SMEM = 4 * 32768;
    cudaFuncSetAttribute(k_gemm_mma, cudaFuncAttributeMaxDynamicSharedMemorySize, GEMM_SMEM);

    const unsigned char* img0h = wimg;
    const unsigned char* img0l = wimg + 32768;
    const unsigned char* img1h = wimg + 2 * 32768;
    const unsigned char* img1l = wimg + 3 * 32768;
    const unsigned char* img2h = wimg + 4 * 32768;
    const unsigned char* img2l = wimg + 5 * 32768;

    // CSR build (both graphs) + W prep
    k_zero<<<cdiv(nf, 256), 256>>>(cntf, cntp, nz, nf, np);
    k_prepW<<<cdiv(3 * 128 * 128, 256), 256>>>(W0, W1, W2);
    k_hist2<<<cdiv(Ef + Ep, 256), 256>>>(ei + Ef, Ef, cntf, pei + Ep, Ep, cntp);
    k_scan2<<<2, 1024>>>(cntf, rpf, curf, dinvf, nf, cntp, rpp, curp, dinvp, np);
    k_place2<<<cdiv(Ef + Ep, 256), 256>>>(ei, ei + Ef, Ef, curf, esrcf,
                                          pei, pei + Ep, Ep, curp, esrcp);

    // conv0 (pooled)
    k_gemm_mma<<<cdiv(np, 128), 256, GEMM_SMEM>>>(px, img0h, img0l, buf1, np);
    k_gather<<<cdiv(np, 8), 256>>>(rpp, esrcp, dinvp, buf1, b0, nullptr, buf2, np);

    // conv1: GEMM on compact rows, scatter into full table (nz-guarded), sparse gather
    k_gemm_mma<<<cdiv(np, 128), 256, GEMM_SMEM>>>(buf2, img1h, img1l, buf1, np);
    k_scatter<<<cdiv(np * 32, 256), 256>>>(buf1, unpool, buf3, nz, np);
    k_gather<<<cdiv(nf, 8), 256>>>(rpf, esrcf, dinvf, buf3, b1, nz, buf2, nf);

    // conv2: full GEMM + gather -> out
    k_gemm_mma<<<cdiv(nf, 128), 256, GEMM_SMEM>>>(buf2, img2h, img2l, buf1, nf);
    k_gather<<<cdiv(nf, 8), 256>>>(rpf, esrcf, dinvf, buf1, b2, nullptr, out, nf);
}

// round 5
// speedup vs baseline: 3.5108x; 1.5170x over previous
#include <cuda_runtime.h>
#include <cuda_bf16.h>
#include <math.h>
#include <stdint.h>

#define D 128
#define NF_MAX 50000
#define NP_MAX 12500
#define EF_MAX 600000

// ---------------- scratch (static device globals) ----------------
__device__ float g_buf1[(size_t)NF_MAX * D];
__device__ float g_buf2[(size_t)NF_MAX * D];
__device__ float g_buf3[(size_t)NF_MAX * D];
__device__ int   g_cntf[NF_MAX];
__device__ int   g_rpf[NF_MAX + 1];
__device__ int   g_curf[NF_MAX];
__device__ int   g_esrcf[EF_MAX];
__device__ float g_dinvf[NF_MAX];
__device__ int   g_cntp[NP_MAX];
__device__ int   g_rpp[NP_MAX + 1];
__device__ int   g_curp[NP_MAX];
__device__ int   g_esrcp[EF_MAX / 4];
__device__ float g_dinvp[NP_MAX];
__device__ unsigned char g_nz[NF_MAX];
__device__ int   g_bsf[64];
__device__ int   g_bsp[64];
// pre-transposed, split, swizzled bf16 W images: [matrix][hi/lo][32KB]
__device__ unsigned char g_wimg[3][2][32768];

static inline int cdiv(int a, int b) { return (a + b - 1) / b; }

// swizzled byte offset inside a [128 rows x 128 k] bf16 tile, row stride 256B.
__host__ __device__ __forceinline__ uint32_t swz(int row, int kbyte) {
    return (uint32_t)(row * 256 + (kbyte ^ ((row & 7) << 4)));
}

__device__ __forceinline__ uint32_t smem_u32(const void* p) {
    uint32_t a;
    asm("{ .reg .u64 t; cvta.to.shared.u64 t, %1; cvt.u32.u64 %0, t; }" : "=r"(a) : "l"(p));
    return a;
}
__device__ __forceinline__ void ldmx4(uint32_t* r, uint32_t addr) {
    asm volatile("ldmatrix.sync.aligned.m8n8.x4.shared.b16 {%0,%1,%2,%3}, [%4];"
                 : "=r"(r[0]), "=r"(r[1]), "=r"(r[2]), "=r"(r[3]) : "r"(addr));
}
__device__ __forceinline__ void mma16816(float* c, const uint32_t* a, uint32_t b0, uint32_t b1) {
    asm volatile("mma.sync.aligned.m16n8k16.row.col.f32.bf16.bf16.f32 "
                 "{%0,%1,%2,%3}, {%4,%5,%6,%7}, {%8,%9}, {%0,%1,%2,%3};"
                 : "+f"(c[0]), "+f"(c[1]), "+f"(c[2]), "+f"(c[3])
                 : "r"(a[0]), "r"(a[1]), "r"(a[2]), "r"(a[3]), "r"(b0), "r"(b1));
}

// ================= CSR build =================
__global__ void k_zero(int* cntf, int* cntp, unsigned char* nz, int nf, int np) {
    int i = blockIdx.x * blockDim.x + threadIdx.x;
    if (i < nf) { cntf[i] = 0; nz[i] = 0; }
    if (i < np) cntp[i] = 0;
}

__global__ void k_hist2(const int* __restrict__ dstf, int Ef, int* __restrict__ cntf,
                        const int* __restrict__ dstp, int Ep, int* __restrict__ cntp) {
    int e = blockIdx.x * blockDim.x + threadIdx.x;
    if (e < Ef) atomicAdd(&cntf[dstf[e]], 1);
    else if (e < Ef + Ep) atomicAdd(&cntp[dstp[e - Ef]], 1);
}

// phase 1: per-block (1024 elems) sums; blocks [0,nbf) full, [nbf,nbf+nbp) pooled
__global__ void k_bsum(const int* __restrict__ cntf, int nf, int nbf, int* __restrict__ bsf,
                       const int* __restrict__ cntp, int np, int* __restrict__ bsp) {
    bool pooled = (int)blockIdx.x >= nbf;
    const int* cnt = pooled ? cntp : cntf;
    int n = pooled ? np : nf;
    int b = pooled ? blockIdx.x - nbf : blockIdx.x;
    int* bs = pooled ? bsp : bsf;
    int tid = threadIdx.x, lane = tid & 31, warp = tid >> 5;
    int i0 = b * 1024 + tid * 4;
    int s = 0;
#pragma unroll
    for (int k = 0; k < 4; k++) if (i0 + k < n) s += cnt[i0 + k];
#pragma unroll
    for (int off = 16; off > 0; off >>= 1) s += __shfl_down_sync(0xffffffffu, s, off);
    __shared__ int ws[8];
    if (lane == 0) ws[warp] = s;
    __syncthreads();
    if (tid == 0) {
        int t = 0;
#pragma unroll
        for (int w = 0; w < 8; w++) t += ws[w];
        bs[b] = t;
    }
}

// phase 2: scan <=64 block sums (grid=2: block 0 full, block 1 pooled); writes rp[n]
__global__ void k_scanbs(int* __restrict__ bsf, int nbf, int* __restrict__ rpf, int nf,
                         int* __restrict__ bsp, int nbp, int* __restrict__ rpp, int np) {
    int* bs = blockIdx.x ? bsp : bsf;
    int nb = blockIdx.x ? nbp : nbf;
    int* rpend = blockIdx.x ? (rpp + np) : (rpf + nf);
    int t = threadIdx.x, lane = t & 31, warp = t >> 5;
    int v = (t < nb) ? bs[t] : 0;
    int inc = v;
#pragma unroll
    for (int off = 1; off < 32; off <<= 1) {
        int u = __shfl_up_sync(0xffffffffu, inc, off);
        if (lane >= off) inc += u;
    }
    __shared__ int w0sum;
    if (warp == 0 && lane == 31) w0sum = inc;
    __syncthreads();
    if (warp == 1) inc += w0sum;
    if (t < nb) bs[t] = inc - v;     // exclusive block offset
    if (t == 63) *rpend = inc;       // grand total
}

// phase 3: block-level exclusive scan + write rp/cur/dinv
__global__ void k_write(const int* __restrict__ cntf, int nf, int nbf,
                        const int* __restrict__ bsf, int* __restrict__ rpf,
                        int* __restrict__ curf, float* __restrict__ dinvf,
                        const int* __restrict__ cntp, int np,
                        const int* __restrict__ bsp, int* __restrict__ rpp,
                        int* __restrict__ curp, float* __restrict__ dinvp) {
    bool pooled = (int)blockIdx.x >= nbf;
    const int* cnt = pooled ? cntp : cntf;
    const int* bs = pooled ? bsp : bsf;
    int* rp = pooled ? rpp : rpf;
    int* cur = pooled ? curp : curf;
    float* dinv = pooled ? dinvp : dinvf;
    int n = pooled ? np : nf;
    int b = pooled ? blockIdx.x - nbf : blockIdx.x;
    int tid = threadIdx.x, lane = tid & 31, warp = tid >> 5;
    int i0 = b * 1024 + tid * 4;
    int v[4];
#pragma unroll
    for (int k = 0; k < 4; k++) v[k] = (i0 + k < n) ? cnt[i0 + k] : 0;
    int s = v[0] + v[1] + v[2] + v[3];
    int inc = s;
#pragma unroll
    for (int off = 1; off < 32; off <<= 1) {
        int u = __shfl_up_sync(0xffffffffu, inc, off);
        if (lane >= off) inc += u;
    }
    __shared__ int ws[8];
    if (lane == 31) ws[warp] = inc;
    __syncthreads();
    int woff = 0;
#pragma unroll
    for (int w = 0; w < 8; w++) if (w < warp) woff += ws[w];
    int pre = bs[b] + woff + inc - s;   // exclusive prefix of first element
#pragma unroll
    for (int k = 0; k < 4; k++) {
        int i = i0 + k;
        if (i < n) {
            rp[i] = pre; cur[i] = pre;
            dinv[i] = rsqrtf((float)v[k] + 1.0f);
            pre += v[k];
        }
    }
}

__global__ void k_place2(const int* __restrict__ srcf, const int* __restrict__ dstf, int Ef,
                         int* __restrict__ curf, int* __restrict__ esrcf,
                         const int* __restrict__ srcp, const int* __restrict__ dstp, int Ep,
                         int* __restrict__ curp, int* __restrict__ esrcp) {
    int e = blockIdx.x * blockDim.x + threadIdx.x;
    if (e < Ef) {
        int p = atomicAdd(&curf[dstf[e]], 1);
        esrcf[p] = srcf[e];
    } else if (e < Ef + Ep) {
        int i = e - Ef;
        int p = atomicAdd(&curp[dstp[i]], 1);
        esrcp[p] = srcp[i];
    }
}

// ================= W -> transposed, split, swizzled bf16 images =================
__global__ void k_prepW(const float* __restrict__ W0, const float* __restrict__ W1,
                        const float* __restrict__ W2) {
    int idx = blockIdx.x * blockDim.x + threadIdx.x;
    if (idx >= 3 * 128 * 128) return;
    int w = idx >> 14, rem = idx & 16383;
    int k = rem >> 7, n = rem & 127;
    const float* W = (w == 0) ? W0 : (w == 1) ? W1 : W2;
    float v = W[k * 128 + n];
    __nv_bfloat16 hb = __float2bfloat16(v);
    float r = v - __bfloat162float(hb);
    __nv_bfloat16 lb = __float2bfloat16(r);
    uint32_t sw = swz(n, k * 2);
    *(unsigned short*)(&g_wimg[w][0][sw]) = __bfloat16_as_ushort(hb);
    *(unsigned short*)(&g_wimg[w][1][sw]) = __bfloat16_as_ushort(lb);
}

// ================= tensor-core GEMM via mma.sync bf16-split =================
__global__ void __launch_bounds__(256, 1) k_gemm_mma(
    const float* __restrict__ A, const unsigned char* __restrict__ Whi,
    const unsigned char* __restrict__ Wlo, float* __restrict__ C, int n) {
    extern __shared__ unsigned char sm[];
    const int OFF_AHI = 0, OFF_ALO = 32768, OFF_BHI = 65536, OFF_BLO = 98304;
    const uint32_t smb = smem_u32(sm);
    const int tid = threadIdx.x, wid = tid >> 5, lane = tid & 31;
    const int row0 = blockIdx.x * 128;

    for (int i = tid; i < 2048; i += 256) {
        ((float4*)(sm + OFF_BHI))[i] = ((const float4*)Whi)[i];
        ((float4*)(sm + OFF_BLO))[i] = ((const float4*)Wlo)[i];
    }
    {
        int row = tid >> 1, half = tid & 1;
        int gr = row0 + row;
        const float4* Arow = (const float4*)(A + (size_t)gr * D) + half * 16;
        unsigned char* ahi = sm + OFF_AHI;
        unsigned char* alo = sm + OFF_ALO;
#pragma unroll
        for (int q = 0; q < 16; q++) {
            float4 v = (gr < n) ? Arow[q] : make_float4(0.f, 0.f, 0.f, 0.f);
            float f[4] = {v.x, v.y, v.z, v.w};
#pragma unroll
            for (int p = 0; p < 2; p++) {
                float a0 = f[p * 2], a1 = f[p * 2 + 1];
                __nv_bfloat16 h0 = __float2bfloat16(a0), h1 = __float2bfloat16(a1);
                float r0 = a0 - __bfloat162float(h0);
                float r1 = a1 - __bfloat162float(h1);
                __nv_bfloat16 l0 = __float2bfloat16(r0), l1 = __float2bfloat16(r1);
                uint32_t uhi = (uint32_t)__bfloat16_as_ushort(h0) | ((uint32_t)__bfloat16_as_ushort(h1) << 16);
                uint32_t ulo = (uint32_t)__bfloat16_as_ushort(l0) | ((uint32_t)__bfloat16_as_ushort(l1) << 16);
                int k = half * 64 + q * 4 + p * 2;
                uint32_t sw = swz(row, k * 2);
                *(uint32_t*)(ahi + sw) = uhi;
                *(uint32_t*)(alo + sw) = ulo;
            }
        }
    }
    __syncthreads();

    const int m0 = wid * 16;
    float acc[16][4];
#pragma unroll
    for (int t = 0; t < 16; t++)
#pragma unroll
        for (int q = 0; q < 4; q++) acc[t][q] = 0.f;

    const int a_row = m0 + (lane & 15);
    const uint32_t a_base = smb + (uint32_t)(a_row * 256);
    const int a_swrow = (a_row & 7) << 4;
    const int a_kadd = (lane >> 4) * 16;
    const int b_rowoff = (lane & 7) + (lane >> 4) * 8;
    const int b_kadd = ((lane >> 3) & 1) * 16;

#pragma unroll 2
    for (int k0 = 0; k0 < 8; k0++) {
        const int kb = k0 * 32;
        uint32_t ahi[4], alo[4];
        uint32_t a_off = (uint32_t)((kb + a_kadd) ^ a_swrow);
        ldmx4(ahi, a_base + OFF_AHI + a_off);
        ldmx4(alo, a_base + OFF_ALO + a_off);
#pragma unroll
        for (int ntp = 0; ntp < 8; ntp++) {
            const int n0 = ntp * 16;
            const int b_row = n0 + b_rowoff;
            uint32_t b_off = (uint32_t)(b_row * 256 + ((kb + b_kadd) ^ ((b_row & 7) << 4)));
            uint32_t bh[4], bl[4];
            ldmx4(bh, smb + OFF_BHI + b_off);
            ldmx4(bl, smb + OFF_BLO + b_off);
            mma16816(acc[2 * ntp],     ahi, bh[0], bh[1]);
            mma16816(acc[2 * ntp + 1], ahi, bh[2], bh[3]);
            mma16816(acc[2 * ntp],     ahi, bl[0], bl[1]);
            mma16816(acc[2 * ntp + 1], ahi, bl[2], bl[3]);
            mma16816(acc[2 * ntp],     alo, bh[0], bh[1]);
            mma16816(acc[2 * ntp + 1], alo, bh[2], bh[3]);
        }
    }

    const int r_lo = row0 + m0 + (lane >> 2);
    const int cbase = (lane & 3) * 2;
    if (r_lo < n) {
        float* crow = C + (size_t)r_lo * D;
#pragma unroll
        for (int t = 0; t < 16; t++)
            *(float2*)(crow + t * 8 + cbase) = make_float2(acc[t][0], acc[t][1]);
    }
    const int r_hi = r_lo + 8;
    if (r_hi < n) {
        float* crow = C + (size_t)r_hi * D;
#pragma unroll
        for (int t = 0; t < 16; t++)
            *(float2*)(crow + t * 8 + cbase) = make_float2(acc[t][2], acc[t][3]);
    }
}

// ================= CSR gather (fused norm + self loop + bias + ELU) =================
__global__ void k_gather(const int* __restrict__ rp, const int* __restrict__ esrc,
                         const float* __restrict__ dinv, const float* __restrict__ xw,
                         const float* __restrict__ bias, const unsigned char* __restrict__ nz,
                         float* __restrict__ out, int n) {
    int row = blockIdx.x * (blockDim.x >> 5) + (threadIdx.x >> 5);
    if (row >= n) return;
    int lane = threadIdx.x & 31;
    float di = dinv[row];
    float4 acc = make_float4(0.f, 0.f, 0.f, 0.f);
    if (!nz || nz[row]) {
        float4 v = reinterpret_cast<const float4*>(xw + (size_t)row * D)[lane];
        float w = di * di;
        acc.x = v.x * w; acc.y = v.y * w; acc.z = v.z * w; acc.w = v.w * w;
    }
    int s0 = rp[row], s1 = rp[row + 1];
    for (int base = s0; base < s1; base += 32) {
        int cnt = min(32, s1 - base);
        int sid = 0; float dv = 0.f; int fl = 1;
        if (lane < cnt) {
            sid = esrc[base + lane];
            dv = dinv[sid];
            if (nz) fl = nz[sid];
        }
        for (int j = 0; j < cnt; j++) {
            int s   = __shfl_sync(0xffffffffu, sid, j);
            int f   = __shfl_sync(0xffffffffu, fl, j);
            float w = __shfl_sync(0xffffffffu, dv, j) * di;
            if (!f) continue;
            float4 v = reinterpret_cast<const float4*>(xw + (size_t)s * D)[lane];
            acc.x += v.x * w; acc.y += v.y * w; acc.z += v.z * w; acc.w += v.w * w;
        }
    }
    float4 bb = reinterpret_cast<const float4*>(bias)[lane];
    acc.x += bb.x; acc.y += bb.y; acc.z += bb.z; acc.w += bb.w;
    acc.x = acc.x > 0.f ? acc.x : expm1f(acc.x);
    acc.y = acc.y > 0.f ? acc.y : expm1f(acc.y);
    acc.z = acc.z > 0.f ? acc.z : expm1f(acc.z);
    acc.w = acc.w > 0.f ? acc.w : expm1f(acc.w);
    reinterpret_cast<float4*>(out)[(size_t)row * 32 + lane] = acc;
}

// ================= unpool scatter =================
__global__ void k_scatter(const float* __restrict__ hw, const int* __restrict__ unpool,
                          float* __restrict__ xwf, unsigned char* __restrict__ nz, int np) {
    int idx = blockIdx.x * blockDim.x + threadIdx.x;
    if (idx >= np * 32) return;
    int r = idx >> 5, q = idx & 31;
    int orow = unpool[r];
    reinterpret_cast<float4*>(xwf)[(size_t)orow * 32 + q] =
        reinterpret_cast<const float4*>(hw)[(size_t)r * 32 + q];
    if (q == 0) nz[orow] = 1;
}

extern "C" void kernel_launch(void* const* d_in, const int* in_sizes, int n_in,
                              void* d_out, int out_size) {
    const int*   ei     = (const int*)d_in[1];
    const float* px     = (const float*)d_in[2];
    const int*   pei    = (const int*)d_in[3];
    const int*   unpool = (const int*)d_in[4];
    const float* W0 = (const float*)d_in[5];
    const float* b0 = (const float*)d_in[6];
    const float* W1 = (const float*)d_in[7];
    const float* b1 = (const float*)d_in[8];
    const float* W2 = (const float*)d_in[9];
    const float* b2 = (const float*)d_in[10];

    const int nf = in_sizes[0] / D;
    const int Ef = in_sizes[1] / 2;
    const int np = in_sizes[2] / D;
    const int Ep = in_sizes[3] / 2;
    float* out = (float*)d_out;

    float *buf1, *buf2, *buf3, *dinvf, *dinvp;
    int *cntf, *rpf, *curf, *esrcf, *cntp, *rpp, *curp, *esrcp, *bsf, *bsp;
    unsigned char *nz, *wimg;
    cudaGetSymbolAddress((void**)&buf1,  g_buf1);
    cudaGetSymbolAddress((void**)&buf2,  g_buf2);
    cudaGetSymbolAddress((void**)&buf3,  g_buf3);
    cudaGetSymbolAddress((void**)&cntf,  g_cntf);
    cudaGetSymbolAddress((void**)&rpf,   g_rpf);
    cudaGetSymbolAddress((void**)&curf,  g_curf);
    cudaGetSymbolAddress((void**)&esrcf, g_esrcf);
    cudaGetSymbolAddress((void**)&dinvf, g_dinvf);
    cudaGetSymbolAddress((void**)&cntp,  g_cntp);
    cudaGetSymbolAddress((void**)&rpp,   g_rpp);
    cudaGetSymbolAddress((void**)&curp,  g_curp);
    cudaGetSymbolAddress((void**)&esrcp, g_esrcp);
    cudaGetSymbolAddress((void**)&dinvp, g_dinvp);
    cudaGetSymbolAddress((void**)&nz,    g_nz);
    cudaGetSymbolAddress((void**)&bsf,   g_bsf);
    cudaGetSymbolAddress((void**)&bsp,   g_bsp);
    cudaGetSymbolAddress((void**)&wimg,  g_wimg);

    const int GEMM_SMEM = 4 * 32768;
    cudaFuncSetAttribute(k_gemm_mma, cudaFuncAttributeMaxDynamicSharedMemorySize, GEMM_SMEM);

    const unsigned char* img0h = wimg;
    const unsigned char* img0l = wimg + 32768;
    const unsigned char* img1h = wimg + 2 * 32768;
    const unsigned char* img1l = wimg + 3 * 32768;
    const unsigned char* img2h = wimg + 4 * 32768;
    const unsigned char* img2l = wimg + 5 * 32768;

    const int nbf = cdiv(nf, 1024), nbp = cdiv(np, 1024);

    // CSR build (both graphs) + W prep
    k_zero<<<cdiv(nf, 256), 256>>>(cntf, cntp, nz, nf, np);
    k_prepW<<<cdiv(3 * 128 * 128, 256), 256>>>(W0, W1, W2);
    k_hist2<<<cdiv(Ef + Ep, 256), 256>>>(ei + Ef, Ef, cntf, pei + Ep, Ep, cntp);
    k_bsum<<<nbf + nbp, 256>>>(cntf, nf, nbf, bsf, cntp, np, bsp);
    k_scanbs<<<2, 64>>>(bsf, nbf, rpf, nf, bsp, nbp, rpp, np);
    k_write<<<nbf + nbp, 256>>>(cntf, nf, nbf, bsf, rpf, curf, dinvf,
                                cntp, np, bsp, rpp, curp, dinvp);
    k_place2<<<cdiv(Ef + Ep, 256), 256>>>(ei, ei + Ef, Ef, curf, esrcf,
                                          pei, pei + Ep, Ep, curp, esrcp);

    // conv0 (pooled)
    k_gemm_mma<<<cdiv(np, 128), 256, GEMM_SMEM>>>(px, img0h, img0l, buf1, np);
    k_gather<<<cdiv(np, 8), 256>>>(rpp, esrcp, dinvp, buf1, b0, nullptr, buf2, np);

    // conv1: GEMM on compact rows, scatter into full table (nz-guarded), sparse gather
    k_gemm_mma<<<cdiv(np, 128), 256, GEMM_SMEM>>>(buf2, img1h, img1l, buf1, np);
    k_scatter<<<cdiv(np * 32, 256), 256>>>(buf1, unpool, buf3, nz, np);
    k_gather<<<cdiv(nf, 8), 256>>>(rpf, esrcf, dinvf, buf3, b1, nz, buf2, nf);

    // conv2: full GEMM + gather -> out
    k_gemm_mma<<<cdiv(nf, 128), 256, GEMM_SMEM>>>(buf2, img2h, img2l, buf1, nf);
    k_gather<<<cdiv(nf, 8), 256>>>(rpf, esrcf, dinvf, buf1, b2, nullptr, out, nf);
}

// round 6
// speedup vs baseline: 4.0564x; 1.1554x over previous
#include <cuda_runtime.h>
#include <cuda_bf16.h>
#include <math.h>
#include <stdint.h>

#define D 128
#define NF_MAX 50000
#define NP_MAX 12500
#define EF_MAX 600000

// ---------------- scratch (static device globals) ----------------
__device__ float g_buf1[(size_t)NF_MAX * D];
__device__ float g_buf2[(size_t)NF_MAX * D];
__device__ int   g_cntf[NF_MAX];
__device__ int   g_rpf[NF_MAX + 1];
__device__ int   g_curf[NF_MAX];
__device__ int   g_esrcf[EF_MAX];
__device__ float g_dinvf[NF_MAX];
__device__ int   g_cntp[NP_MAX];
__device__ int   g_rpp[NP_MAX + 1];
__device__ int   g_curp[NP_MAX];
__device__ int   g_esrcp[EF_MAX / 4];
__device__ float g_dinvp[NP_MAX];
__device__ int   g_inv[NF_MAX];
__device__ int   g_bsf[64];
__device__ int   g_bsp[64];
// pre-transposed, split, swizzled bf16 W images: [matrix][hi/lo][32KB]
__device__ unsigned char g_wimg[3][2][32768];

static inline int cdiv(int a, int b) { return (a + b - 1) / b; }

__host__ __device__ __forceinline__ uint32_t swz(int row, int kbyte) {
    return (uint32_t)(row * 256 + (kbyte ^ ((row & 7) << 4)));
}

__device__ __forceinline__ uint32_t smem_u32(const void* p) {
    uint32_t a;
    asm("{ .reg .u64 t; cvta.to.shared.u64 t, %1; cvt.u32.u64 %0, t; }" : "=r"(a) : "l"(p));
    return a;
}
__device__ __forceinline__ void ldmx4(uint32_t* r, uint32_t addr) {
    asm volatile("ldmatrix.sync.aligned.m8n8.x4.shared.b16 {%0,%1,%2,%3}, [%4];"
                 : "=r"(r[0]), "=r"(r[1]), "=r"(r[2]), "=r"(r[3]) : "r"(addr));
}
__device__ __forceinline__ void mma16816(float* c, const uint32_t* a, uint32_t b0, uint32_t b1) {
    asm volatile("mma.sync.aligned.m16n8k16.row.col.f32.bf16.bf16.f32 "
                 "{%0,%1,%2,%3}, {%4,%5,%6,%7}, {%8,%9}, {%0,%1,%2,%3};"
                 : "+f"(c[0]), "+f"(c[1]), "+f"(c[2]), "+f"(c[3])
                 : "r"(a[0]), "r"(a[1]), "r"(a[2]), "r"(a[3]), "r"(b0), "r"(b1));
}

// ================= fused zero + W-prep =================
__global__ void k_zero_prep(int* cntf, int* cntp, int* inv, int nf, int np,
                            const float* __restrict__ W0, const float* __restrict__ W1,
                            const float* __restrict__ W2) {
    int i = blockIdx.x * blockDim.x + threadIdx.x;
    if (i < nf) { cntf[i] = 0; inv[i] = -1; }
    if (i < np) cntp[i] = 0;
    if (i < 3 * 128 * 128) {
        int w = i >> 14, rem = i & 16383;
        int k = rem >> 7, n = rem & 127;
        const float* W = (w == 0) ? W0 : (w == 1) ? W1 : W2;
        float v = W[k * 128 + n];
        __nv_bfloat16 hb = __float2bfloat16(v);
        float r = v - __bfloat162float(hb);
        __nv_bfloat16 lb = __float2bfloat16(r);
        uint32_t sw = swz(n, k * 2);
        *(unsigned short*)(&g_wimg[w][0][sw]) = __bfloat16_as_ushort(hb);
        *(unsigned short*)(&g_wimg[w][1][sw]) = __bfloat16_as_ushort(lb);
    }
}

__global__ void k_inv(const int* __restrict__ unpool, int* __restrict__ inv, int np) {
    int r = blockIdx.x * blockDim.x + threadIdx.x;
    if (r < np) inv[unpool[r]] = r;
}

__global__ void k_hist2(const int* __restrict__ dstf, int Ef, int* __restrict__ cntf,
                        const int* __restrict__ dstp, int Ep, int* __restrict__ cntp) {
    int e = blockIdx.x * blockDim.x + threadIdx.x;
    if (e < Ef) atomicAdd(&cntf[dstf[e]], 1);
    else if (e < Ef + Ep) atomicAdd(&cntp[dstp[e - Ef]], 1);
}

__global__ void k_bsum(const int* __restrict__ cntf, int nf, int nbf, int* __restrict__ bsf,
                       const int* __restrict__ cntp, int np, int* __restrict__ bsp) {
    bool pooled = (int)blockIdx.x >= nbf;
    const int* cnt = pooled ? cntp : cntf;
    int n = pooled ? np : nf;
    int b = pooled ? blockIdx.x - nbf : blockIdx.x;
    int* bs = pooled ? bsp : bsf;
    int tid = threadIdx.x, lane = tid & 31, warp = tid >> 5;
    int i0 = b * 1024 + tid * 4;
    int s = 0;
#pragma unroll
    for (int k = 0; k < 4; k++) if (i0 + k < n) s += cnt[i0 + k];
#pragma unroll
    for (int off = 16; off > 0; off >>= 1) s += __shfl_down_sync(0xffffffffu, s, off);
    __shared__ int ws[8];
    if (lane == 0) ws[warp] = s;
    __syncthreads();
    if (tid == 0) {
        int t = 0;
#pragma unroll
        for (int w = 0; w < 8; w++) t += ws[w];
        bs[b] = t;
    }
}

__global__ void k_scanbs(int* __restrict__ bsf, int nbf, int* __restrict__ rpf, int nf,
                         int* __restrict__ bsp, int nbp, int* __restrict__ rpp, int np) {
    int* bs = blockIdx.x ? bsp : bsf;
    int nb = blockIdx.x ? nbp : nbf;
    int* rpend = blockIdx.x ? (rpp + np) : (rpf + nf);
    int t = threadIdx.x, lane = t & 31, warp = t >> 5;
    int v = (t < nb) ? bs[t] : 0;
    int inc = v;
#pragma unroll
    for (int off = 1; off < 32; off <<= 1) {
        int u = __shfl_up_sync(0xffffffffu, inc, off);
        if (lane >= off) inc += u;
    }
    __shared__ int w0sum;
    if (warp == 0 && lane == 31) w0sum = inc;
    __syncthreads();
    if (warp == 1) inc += w0sum;
    if (t < nb) bs[t] = inc - v;
    if (t == 63) *rpend = inc;
}

__global__ void k_write(const int* __restrict__ cntf, int nf, int nbf,
                        const int* __restrict__ bsf, int* __restrict__ rpf,
                        int* __restrict__ curf, float* __restrict__ dinvf,
                        const int* __restrict__ cntp, int np,
                        const int* __restrict__ bsp, int* __restrict__ rpp,
                        int* __restrict__ curp, float* __restrict__ dinvp) {
    bool pooled = (int)blockIdx.x >= nbf;
    const int* cnt = pooled ? cntp : cntf;
    const int* bs = pooled ? bsp : bsf;
    int* rp = pooled ? rpp : rpf;
    int* cur = pooled ? curp : curf;
    float* dinv = pooled ? dinvp : dinvf;
    int n = pooled ? np : nf;
    int b = pooled ? blockIdx.x - nbf : blockIdx.x;
    int tid = threadIdx.x, lane = tid & 31, warp = tid >> 5;
    int i0 = b * 1024 + tid * 4;
    int v[4];
#pragma unroll
    for (int k = 0; k < 4; k++) v[k] = (i0 + k < n) ? cnt[i0 + k] : 0;
    int s = v[0] + v[1] + v[2] + v[3];
    int inc = s;
#pragma unroll
    for (int off = 1; off < 32; off <<= 1) {
        int u = __shfl_up_sync(0xffffffffu, inc, off);
        if (lane >= off) inc += u;
    }
    __shared__ int ws[8];
    if (lane == 31) ws[warp] = inc;
    __syncthreads();
    int woff = 0;
#pragma unroll
    for (int w = 0; w < 8; w++) if (w < warp) woff += ws[w];
    int pre = bs[b] + woff + inc - s;
#pragma unroll
    for (int k = 0; k < 4; k++) {
        int i = i0 + k;
        if (i < n) {
            rp[i] = pre; cur[i] = pre;
            dinv[i] = rsqrtf((float)v[k] + 1.0f);
            pre += v[k];
        }
    }
}

__global__ void k_place2(const int* __restrict__ srcf, const int* __restrict__ dstf, int Ef,
                         int* __restrict__ curf, int* __restrict__ esrcf,
                         const int* __restrict__ srcp, const int* __restrict__ dstp, int Ep,
                         int* __restrict__ curp, int* __restrict__ esrcp) {
    int e = blockIdx.x * blockDim.x + threadIdx.x;
    if (e < Ef) {
        int p = atomicAdd(&curf[dstf[e]], 1);
        esrcf[p] = srcf[e];
    } else if (e < Ef + Ep) {
        int i = e - Ef;
        int p = atomicAdd(&curp[dstp[i]], 1);
        esrcp[p] = srcp[i];
    }
}

// ================= tensor-core GEMM via mma.sync bf16-split =================
__global__ void __launch_bounds__(256, 1) k_gemm_mma(
    const float* __restrict__ A, const unsigned char* __restrict__ Whi,
    const unsigned char* __restrict__ Wlo, float* __restrict__ C, int n) {
    extern __shared__ unsigned char sm[];
    const int OFF_AHI = 0, OFF_ALO = 32768, OFF_BHI = 65536, OFF_BLO = 98304;
    const uint32_t smb = smem_u32(sm);
    const int tid = threadIdx.x, wid = tid >> 5, lane = tid & 31;
    const int row0 = blockIdx.x * 128;

    for (int i = tid; i < 2048; i += 256) {
        ((float4*)(sm + OFF_BHI))[i] = ((const float4*)Whi)[i];
        ((float4*)(sm + OFF_BLO))[i] = ((const float4*)Wlo)[i];
    }
    {
        int row = tid >> 1, half = tid & 1;
        int gr = row0 + row;
        const float4* Arow = (const float4*)(A + (size_t)gr * D) + half * 16;
        unsigned char* ahi = sm + OFF_AHI;
        unsigned char* alo = sm + OFF_ALO;
#pragma unroll
        for (int q = 0; q < 16; q++) {
            float4 v = (gr < n) ? Arow[q] : make_float4(0.f, 0.f, 0.f, 0.f);
            float f[4] = {v.x, v.y, v.z, v.w};
#pragma unroll
            for (int p = 0; p < 2; p++) {
                float a0 = f[p * 2], a1 = f[p * 2 + 1];
                __nv_bfloat16 h0 = __float2bfloat16(a0), h1 = __float2bfloat16(a1);
                float r0 = a0 - __bfloat162float(h0);
                float r1 = a1 - __bfloat162float(h1);
                __nv_bfloat16 l0 = __float2bfloat16(r0), l1 = __float2bfloat16(r1);
                uint32_t uhi = (uint32_t)__bfloat16_as_ushort(h0) | ((uint32_t)__bfloat16_as_ushort(h1) << 16);
                uint32_t ulo = (uint32_t)__bfloat16_as_ushort(l0) | ((uint32_t)__bfloat16_as_ushort(l1) << 16);
                int k = half * 64 + q * 4 + p * 2;
                uint32_t sw = swz(row, k * 2);
                *(uint32_t*)(ahi + sw) = uhi;
                *(uint32_t*)(alo + sw) = ulo;
            }
        }
    }
    __syncthreads();

    const int m0 = wid * 16;
    float acc[16][4];
#pragma unroll
    for (int t = 0; t < 16; t++)
#pragma unroll
        for (int q = 0; q < 4; q++) acc[t][q] = 0.f;

    const int a_row = m0 + (lane & 15);
    const uint32_t a_base = smb + (uint32_t)(a_row * 256);
    const int a_swrow = (a_row & 7) << 4;
    const int a_kadd = (lane >> 4) * 16;
    const int b_rowoff = (lane & 7) + (lane >> 4) * 8;
    const int b_kadd = ((lane >> 3) & 1) * 16;

#pragma unroll 2
    for (int k0 = 0; k0 < 8; k0++) {
        const int kb = k0 * 32;
        uint32_t ahi[4], alo[4];
        uint32_t a_off = (uint32_t)((kb + a_kadd) ^ a_swrow);
        ldmx4(ahi, a_base + OFF_AHI + a_off);
        ldmx4(alo, a_base + OFF_ALO + a_off);
#pragma unroll
        for (int ntp = 0; ntp < 8; ntp++) {
            const int n0 = ntp * 16;
            const int b_row = n0 + b_rowoff;
            uint32_t b_off = (uint32_t)(b_row * 256 + ((kb + b_kadd) ^ ((b_row & 7) << 4)));
            uint32_t bh[4], bl[4];
            ldmx4(bh, smb + OFF_BHI + b_off);
            ldmx4(bl, smb + OFF_BLO + b_off);
            mma16816(acc[2 * ntp],     ahi, bh[0], bh[1]);
            mma16816(acc[2 * ntp + 1], ahi, bh[2], bh[3]);
            mma16816(acc[2 * ntp],     ahi, bl[0], bl[1]);
            mma16816(acc[2 * ntp + 1], ahi, bl[2], bl[3]);
            mma16816(acc[2 * ntp],     alo, bh[0], bh[1]);
            mma16816(acc[2 * ntp + 1], alo, bh[2], bh[3]);
        }
    }

    const int r_lo = row0 + m0 + (lane >> 2);
    const int cbase = (lane & 3) * 2;
    if (r_lo < n) {
        float* crow = C + (size_t)r_lo * D;
#pragma unroll
        for (int t = 0; t < 16; t++)
            *(float2*)(crow + t * 8 + cbase) = make_float2(acc[t][0], acc[t][1]);
    }
    const int r_hi = r_lo + 8;
    if (r_hi < n) {
        float* crow = C + (size_t)r_hi * D;
#pragma unroll
        for (int t = 0; t < 16; t++)
            *(float2*)(crow + t * 8 + cbase) = make_float2(acc[t][2], acc[t][3]);
    }
}

// ================= CSR gather (optional inv-index compact-source mode) =================
__global__ void k_gather(const int* __restrict__ rp, const int* __restrict__ esrc,
                         const float* __restrict__ dinv, const float* __restrict__ xw,
                         const float* __restrict__ bias, const int* __restrict__ inv,
                         float* __restrict__ out, int n) {
    int row = blockIdx.x * (blockDim.x >> 5) + (threadIdx.x >> 5);
    if (row >= n) return;
    int lane = threadIdx.x & 31;
    float di = dinv[row];
    float4 acc = make_float4(0.f, 0.f, 0.f, 0.f);
    // self loop
    {
        int sr = inv ? inv[row] : row;
        if (sr >= 0) {
            float4 v = reinterpret_cast<const float4*>(xw + (size_t)sr * D)[lane];
            float w = di * di;
            acc.x = v.x * w; acc.y = v.y * w; acc.z = v.z * w; acc.w = v.w * w;
        }
    }
    int s0 = rp[row], s1 = rp[row + 1];
    for (int base = s0; base < s1; base += 32) {
        int cnt = min(32, s1 - base);
        int sid = -1; float dv = 0.f;
        if (lane < cnt) {
            int s = esrc[base + lane];
            dv = dinv[s];
            sid = inv ? inv[s] : s;
        }
        for (int j = 0; j < cnt; j++) {
            int s   = __shfl_sync(0xffffffffu, sid, j);
            float w = __shfl_sync(0xffffffffu, dv, j) * di;
            if (s < 0) continue;
            float4 v = reinterpret_cast<const float4*>(xw + (size_t)s * D)[lane];
            acc.x += v.x * w; acc.y += v.y * w; acc.z += v.z * w; acc.w += v.w * w;
        }
    }
    float4 bb = reinterpret_cast<const float4*>(bias)[lane];
    acc.x += bb.x; acc.y += bb.y; acc.z += bb.z; acc.w += bb.w;
    acc.x = acc.x > 0.f ? acc.x : expm1f(acc.x);
    acc.y = acc.y > 0.f ? acc.y : expm1f(acc.y);
    acc.z = acc.z > 0.f ? acc.z : expm1f(acc.z);
    acc.w = acc.w > 0.f ? acc.w : expm1f(acc.w);
    reinterpret_cast<float4*>(out)[(size_t)row * 32 + lane] = acc;
}

extern "C" void kernel_launch(void* const* d_in, const int* in_sizes, int n_in,
                              void* d_out, int out_size) {
    const int*   ei     = (const int*)d_in[1];
    const float* px     = (const float*)d_in[2];
    const int*   pei    = (const int*)d_in[3];
    const int*   unpool = (const int*)d_in[4];
    const float* W0 = (const float*)d_in[5];
    const float* b0 = (const float*)d_in[6];
    const float* W1 = (const float*)d_in[7];
    const float* b1 = (const float*)d_in[8];
    const float* W2 = (const float*)d_in[9];
    const float* b2 = (const float*)d_in[10];

    const int nf = in_sizes[0] / D;
    const int Ef = in_sizes[1] / 2;
    const int np = in_sizes[2] / D;
    const int Ep = in_sizes[3] / 2;
    float* out = (float*)d_out;

    float *buf1, *buf2, *dinvf, *dinvp;
    int *cntf, *rpf, *curf, *esrcf, *cntp, *rpp, *curp, *esrcp, *bsf, *bsp, *inv;
    unsigned char* wimg;
    cudaGetSymbolAddress((void**)&buf1,  g_buf1);
    cudaGetSymbolAddress((void**)&buf2,  g_buf2);
    cudaGetSymbolAddress((void**)&cntf,  g_cntf);
    cudaGetSymbolAddress((void**)&rpf,   g_rpf);
    cudaGetSymbolAddress((void**)&curf,  g_curf);
    cudaGetSymbolAddress((void**)&esrcf, g_esrcf);
    cudaGetSymbolAddress((void**)&dinvf, g_dinvf);
    cudaGetSymbolAddress((void**)&cntp,  g_cntp);
    cudaGetSymbolAddress((void**)&rpp,   g_rpp);
    cudaGetSymbolAddress((void**)&curp,  g_curp);
    cudaGetSymbolAddress((void**)&esrcp, g_esrcp);
    cudaGetSymbolAddress((void**)&dinvp, g_dinvp);
    cudaGetSymbolAddress((void**)&inv,   g_inv);
    cudaGetSymbolAddress((void**)&bsf,   g_bsf);
    cudaGetSymbolAddress((void**)&bsp,   g_bsp);
    cudaGetSymbolAddress((void**)&wimg,  g_wimg);

    const int GEMM_SMEM = 4 * 32768;
    cudaFuncSetAttribute(k_gemm_mma, cudaFuncAttributeMaxDynamicSharedMemorySize, GEMM_SMEM);

    const unsigned char* img0h = wimg;
    const unsigned char* img0l = wimg + 32768;
    const unsigned char* img1h = wimg + 2 * 32768;
    const unsigned char* img1l = wimg + 3 * 32768;
    const unsigned char* img2h = wimg + 4 * 32768;
    const unsigned char* img2l = wimg + 5 * 32768;

    const int nbf = cdiv(nf, 1024), nbp = cdiv(np, 1024);

    // side stream + events: created once on the first (uncaptured) correctness call
    static cudaStream_t s1 = nullptr;
    static cudaEvent_t ev_fork = nullptr, ev_join = nullptr;
    if (!s1) {
        cudaStreamCreateWithFlags(&s1, cudaStreamNonBlocking);
        cudaEventCreateWithFlags(&ev_fork, cudaEventDisableTiming);
        cudaEventCreateWithFlags(&ev_join, cudaEventDisableTiming);
    }

    // ---- prologue (legacy stream) ----
    k_zero_prep<<<cdiv(nf, 256), 256>>>(cntf, cntp, inv, nf, np, W0, W1, W2);
    k_inv<<<cdiv(np, 256), 256>>>(unpool, inv, np);

    // fork: GEMM0 (px @ W0) on side stream, CSR build on legacy stream
    cudaEventRecord(ev_fork, 0);
    cudaStreamWaitEvent(s1, ev_fork, 0);
    k_gemm_mma<<<cdiv(np, 128), 256, GEMM_SMEM, s1>>>(px, img0h, img0l, buf1, np);
    cudaEventRecord(ev_join, s1);

    k_hist2<<<cdiv(Ef + Ep, 256), 256>>>(ei + Ef, Ef, cntf, pei + Ep, Ep, cntp);
    k_bsum<<<nbf + nbp, 256>>>(cntf, nf, nbf, bsf, cntp, np, bsp);
    k_scanbs<<<2, 64>>>(bsf, nbf, rpf, nf, bsp, nbp, rpp, np);
    k_write<<<nbf + nbp, 256>>>(cntf, nf, nbf, bsf, rpf, curf, dinvf,
                                cntp, np, bsp, rpp, curp, dinvp);
    k_place2<<<cdiv(Ef + Ep, 256), 256>>>(ei, ei + Ef, Ef, curf, esrcf,
                                          pei, pei + Ep, Ep, curp, esrcp);

    // join
    cudaStreamWaitEvent(0, ev_join, 0);

    // conv0 gather (pooled)
    k_gather<<<cdiv(np, 8), 256>>>(rpp, esrcp, dinvp, buf1, b0, nullptr, buf2, np);

    // conv1: compact GEMM, inv-indexed sparse gather on full graph
    k_gemm_mma<<<cdiv(np, 128), 256, GEMM_SMEM>>>(buf2, img1h, img1l, buf1, np);
    k_gather<<<cdiv(nf, 8), 256>>>(rpf, esrcf, dinvf, buf1, b1, inv, buf2, nf);

    // conv2: full GEMM + gather -> out
    k_gemm_mma<<<cdiv(nf, 128), 256, GEMM_SMEM>>>(buf2, img2h, img2l, buf1, nf);
    k_gather<<<cdiv(nf, 8), 256>>>(rpf, esrcf, dinvf, buf1, b2, nullptr, out, nf);
}

// round 7
// speedup vs baseline: 4.1109x; 1.0134x over previous
#include <cuda_runtime.h>
#include <cuda_bf16.h>
#include <math.h>
#include <stdint.h>

#define D 128
#define NF_MAX 50000
#define NP_MAX 12500
#define EF_MAX 600000

// ---------------- scratch (static device globals) ----------------
__device__ float g_buf1[(size_t)NF_MAX * D];
__device__ float g_buf2[(size_t)NF_MAX * D];
__device__ int   g_cntf[NF_MAX];
__device__ int   g_rpf[NF_MAX + 1];
__device__ int   g_curf[NF_MAX];
__device__ int   g_esrcf[EF_MAX];
__device__ float g_dinvf[NF_MAX];
__device__ int   g_cntp[NP_MAX];
__device__ int   g_rpp[NP_MAX + 1];
__device__ int   g_curp[NP_MAX];
__device__ int   g_esrcp[EF_MAX / 4];
__device__ float g_dinvp[NP_MAX];
__device__ int   g_inv[NF_MAX];
__device__ int   g_bsf[64];
__device__ int   g_bsp[64];
__device__ unsigned char g_wimg[3][2][32768];

static inline int cdiv(int a, int b) { return (a + b - 1) / b; }

__host__ __device__ __forceinline__ uint32_t swz(int row, int kbyte) {
    return (uint32_t)(row * 256 + (kbyte ^ ((row & 7) << 4)));
}

__device__ __forceinline__ uint32_t smem_u32(const void* p) {
    uint32_t a;
    asm("{ .reg .u64 t; cvta.to.shared.u64 t, %1; cvt.u32.u64 %0, t; }" : "=r"(a) : "l"(p));
    return a;
}
__device__ __forceinline__ void ldmx4(uint32_t* r, uint32_t addr) {
    asm volatile("ldmatrix.sync.aligned.m8n8.x4.shared.b16 {%0,%1,%2,%3}, [%4];"
                 : "=r"(r[0]), "=r"(r[1]), "=r"(r[2]), "=r"(r[3]) : "r"(addr));
}
__device__ __forceinline__ void mma16816(float* c, const uint32_t* a, uint32_t b0, uint32_t b1) {
    asm volatile("mma.sync.aligned.m16n8k16.row.col.f32.bf16.bf16.f32 "
                 "{%0,%1,%2,%3}, {%4,%5,%6,%7}, {%8,%9}, {%0,%1,%2,%3};"
                 : "+f"(c[0]), "+f"(c[1]), "+f"(c[2]), "+f"(c[3])
                 : "r"(a[0]), "r"(a[1]), "r"(a[2]), "r"(a[3]), "r"(b0), "r"(b1));
}

// ================= fused zero + W-prep =================
__global__ void k_zero_prep(int* cntf, int* cntp, int* inv, int nf, int np,
                            const float* __restrict__ W0, const float* __restrict__ W1,
                            const float* __restrict__ W2) {
    int i = blockIdx.x * blockDim.x + threadIdx.x;
    if (i < nf) { cntf[i] = 0; inv[i] = -1; }
    if (i < np) cntp[i] = 0;
    if (i < 3 * 128 * 128) {
        int w = i >> 14, rem = i & 16383;
        int k = rem >> 7, n = rem & 127;
        const float* W = (w == 0) ? W0 : (w == 1) ? W1 : W2;
        float v = W[k * 128 + n];
        __nv_bfloat16 hb = __float2bfloat16(v);
        float r = v - __bfloat162float(hb);
        __nv_bfloat16 lb = __float2bfloat16(r);
        uint32_t sw = swz(n, k * 2);
        *(unsigned short*)(&g_wimg[w][0][sw]) = __bfloat16_as_ushort(hb);
        *(unsigned short*)(&g_wimg[w][1][sw]) = __bfloat16_as_ushort(lb);
    }
}

__global__ void k_inv(const int* __restrict__ unpool, int* __restrict__ inv, int np) {
    int r = blockIdx.x * blockDim.x + threadIdx.x;
    if (r < np) inv[unpool[r]] = r;
}

// ================= single-graph CSR kernels =================
__global__ void k_hist(const int* __restrict__ dst, int E, int* __restrict__ cnt) {
    int e = blockIdx.x * blockDim.x + threadIdx.x;
    if (e < E) atomicAdd(&cnt[dst[e]], 1);
}

__global__ void k_bsum(const int* __restrict__ cnt, int n, int* __restrict__ bs) {
    int b = blockIdx.x;
    int tid = threadIdx.x, lane = tid & 31, warp = tid >> 5;
    int i0 = b * 1024 + tid * 4;
    int s = 0;
#pragma unroll
    for (int k = 0; k < 4; k++) if (i0 + k < n) s += cnt[i0 + k];
#pragma unroll
    for (int off = 16; off > 0; off >>= 1) s += __shfl_down_sync(0xffffffffu, s, off);
    __shared__ int ws[8];
    if (lane == 0) ws[warp] = s;
    __syncthreads();
    if (tid == 0) {
        int t = 0;
#pragma unroll
        for (int w = 0; w < 8; w++) t += ws[w];
        bs[b] = t;
    }
}

__global__ void k_scanbs(int* __restrict__ bs, int nb, int* __restrict__ rp, int n) {
    int t = threadIdx.x, lane = t & 31, warp = t >> 5;
    int v = (t < nb) ? bs[t] : 0;
    int inc = v;
#pragma unroll
    for (int off = 1; off < 32; off <<= 1) {
        int u = __shfl_up_sync(0xffffffffu, inc, off);
        if (lane >= off) inc += u;
    }
    __shared__ int w0sum;
    if (warp == 0 && lane == 31) w0sum = inc;
    __syncthreads();
    if (warp == 1) inc += w0sum;
    if (t < nb) bs[t] = inc - v;
    if (t == 63) rp[n] = inc;
}

__global__ void k_write(const int* __restrict__ cnt, int n, const int* __restrict__ bs,
                        int* __restrict__ rp, int* __restrict__ cur, float* __restrict__ dinv) {
    int b = blockIdx.x;
    int tid = threadIdx.x, lane = tid & 31, warp = tid >> 5;
    int i0 = b * 1024 + tid * 4;
    int v[4];
#pragma unroll
    for (int k = 0; k < 4; k++) v[k] = (i0 + k < n) ? cnt[i0 + k] : 0;
    int s = v[0] + v[1] + v[2] + v[3];
    int inc = s;
#pragma unroll
    for (int off = 1; off < 32; off <<= 1) {
        int u = __shfl_up_sync(0xffffffffu, inc, off);
        if (lane >= off) inc += u;
    }
    __shared__ int ws[8];
    if (lane == 31) ws[warp] = inc;
    __syncthreads();
    int woff = 0;
#pragma unroll
    for (int w = 0; w < 8; w++) if (w < warp) woff += ws[w];
    int pre = bs[b] + woff + inc - s;
#pragma unroll
    for (int k = 0; k < 4; k++) {
        int i = i0 + k;
        if (i < n) {
            rp[i] = pre; cur[i] = pre;
            dinv[i] = rsqrtf((float)v[k] + 1.0f);
            pre += v[k];
        }
    }
}

__global__ void k_place(const int* __restrict__ src, const int* __restrict__ dst, int E,
                        int* __restrict__ cur, int* __restrict__ esrc) {
    int e = blockIdx.x * blockDim.x + threadIdx.x;
    if (e < E) {
        int p = atomicAdd(&cur[dst[e]], 1);
        esrc[p] = src[e];
    }
}

// ================= tensor-core GEMM via mma.sync bf16-split =================
__global__ void __launch_bounds__(256, 1) k_gemm_mma(
    const float* __restrict__ A, const unsigned char* __restrict__ Whi,
    const unsigned char* __restrict__ Wlo, float* __restrict__ C, int n) {
    extern __shared__ unsigned char sm[];
    const int OFF_AHI = 0, OFF_ALO = 32768, OFF_BHI = 65536, OFF_BLO = 98304;
    const uint32_t smb = smem_u32(sm);
    const int tid = threadIdx.x, wid = tid >> 5, lane = tid & 31;
    const int row0 = blockIdx.x * 128;

    for (int i = tid; i < 2048; i += 256) {
        ((float4*)(sm + OFF_BHI))[i] = ((const float4*)Whi)[i];
        ((float4*)(sm + OFF_BLO))[i] = ((const float4*)Wlo)[i];
    }
    {
        int row = tid >> 1, half = tid & 1;
        int gr = row0 + row;
        const float4* Arow = (const float4*)(A + (size_t)gr * D) + half * 16;
        unsigned char* ahi = sm + OFF_AHI;
        unsigned char* alo = sm + OFF_ALO;
#pragma unroll
        for (int q = 0; q < 16; q++) {
            float4 v = (gr < n) ? Arow[q] : make_float4(0.f, 0.f, 0.f, 0.f);
            float f[4] = {v.x, v.y, v.z, v.w};
#pragma unroll
            for (int p = 0; p < 2; p++) {
                float a0 = f[p * 2], a1 = f[p * 2 + 1];
                __nv_bfloat16 h0 = __float2bfloat16(a0), h1 = __float2bfloat16(a1);
                float r0 = a0 - __bfloat162float(h0);
                float r1 = a1 - __bfloat162float(h1);
                __nv_bfloat16 l0 = __float2bfloat16(r0), l1 = __float2bfloat16(r1);
                uint32_t uhi = (uint32_t)__bfloat16_as_ushort(h0) | ((uint32_t)__bfloat16_as_ushort(h1) << 16);
                uint32_t ulo = (uint32_t)__bfloat16_as_ushort(l0) | ((uint32_t)__bfloat16_as_ushort(l1) << 16);
                int k = half * 64 + q * 4 + p * 2;
                uint32_t sw = swz(row, k * 2);
                *(uint32_t*)(ahi + sw) = uhi;
                *(uint32_t*)(alo + sw) = ulo;
            }
        }
    }
    __syncthreads();

    const int m0 = wid * 16;
    float acc[16][4];
#pragma unroll
    for (int t = 0; t < 16; t++)
#pragma unroll
        for (int q = 0; q < 4; q++) acc[t][q] = 0.f;

    const int a_row = m0 + (lane & 15);
    const uint32_t a_base = smb + (uint32_t)(a_row * 256);
    const int a_swrow = (a_row & 7) << 4;
    const int a_kadd = (lane >> 4) * 16;
    const int b_rowoff = (lane & 7) + (lane >> 4) * 8;
    const int b_kadd = ((lane >> 3) & 1) * 16;

#pragma unroll 2
    for (int k0 = 0; k0 < 8; k0++) {
        const int kb = k0 * 32;
        uint32_t ahi[4], alo[4];
        uint32_t a_off = (uint32_t)((kb + a_kadd) ^ a_swrow);
        ldmx4(ahi, a_base + OFF_AHI + a_off);
        ldmx4(alo, a_base + OFF_ALO + a_off);
#pragma unroll
        for (int ntp = 0; ntp < 8; ntp++) {
            const int n0 = ntp * 16;
            const int b_row = n0 + b_rowoff;
            uint32_t b_off = (uint32_t)(b_row * 256 + ((kb + b_kadd) ^ ((b_row & 7) << 4)));
            uint32_t bh[4], bl[4];
            ldmx4(bh, smb + OFF_BHI + b_off);
            ldmx4(bl, smb + OFF_BLO + b_off);
            mma16816(acc[2 * ntp],     ahi, bh[0], bh[1]);
            mma16816(acc[2 * ntp + 1], ahi, bh[2], bh[3]);
            mma16816(acc[2 * ntp],     ahi, bl[0], bl[1]);
            mma16816(acc[2 * ntp + 1], ahi, bl[2], bl[3]);
            mma16816(acc[2 * ntp],     alo, bh[0], bh[1]);
            mma16816(acc[2 * ntp + 1], alo, bh[2], bh[3]);
        }
    }

    const int r_lo = row0 + m0 + (lane >> 2);
    const int cbase = (lane & 3) * 2;
    if (r_lo < n) {
        float* crow = C + (size_t)r_lo * D;
#pragma unroll
        for (int t = 0; t < 16; t++)
            *(float2*)(crow + t * 8 + cbase) = make_float2(acc[t][0], acc[t][1]);
    }
    const int r_hi = r_lo + 8;
    if (r_hi < n) {
        float* crow = C + (size_t)r_hi * D;
#pragma unroll
        for (int t = 0; t < 16; t++)
            *(float2*)(crow + t * 8 + cbase) = make_float2(acc[t][2], acc[t][3]);
    }
}

// ================= CSR gather (optional inv-index compact-source mode) =================
__global__ void k_gather(const int* __restrict__ rp, const int* __restrict__ esrc,
                         const float* __restrict__ dinv, const float* __restrict__ xw,
                         const float* __restrict__ bias, const int* __restrict__ inv,
                         float* __restrict__ out, int n) {
    int row = blockIdx.x * (blockDim.x >> 5) + (threadIdx.x >> 5);
    if (row >= n) return;
    int lane = threadIdx.x & 31;
    float di = dinv[row];
    float4 acc = make_float4(0.f, 0.f, 0.f, 0.f);
    {
        int sr = inv ? inv[row] : row;
        if (sr >= 0) {
            float4 v = reinterpret_cast<const float4*>(xw + (size_t)sr * D)[lane];
            float w = di * di;
            acc.x = v.x * w; acc.y = v.y * w; acc.z = v.z * w; acc.w = v.w * w;
        }
    }
    int s0 = rp[row], s1 = rp[row + 1];
    for (int base = s0; base < s1; base += 32) {
        int cnt = min(32, s1 - base);
        int sid = -1; float dv = 0.f;
        if (lane < cnt) {
            int s = esrc[base + lane];
            dv = dinv[s];
            sid = inv ? inv[s] : s;
        }
        for (int j = 0; j < cnt; j++) {
            int s   = __shfl_sync(0xffffffffu, sid, j);
            float w = __shfl_sync(0xffffffffu, dv, j) * di;
            if (s < 0) continue;
            float4 v = reinterpret_cast<const float4*>(xw + (size_t)s * D)[lane];
            acc.x += v.x * w; acc.y += v.y * w; acc.z += v.z * w; acc.w += v.w * w;
        }
    }
    float4 bb = reinterpret_cast<const float4*>(bias)[lane];
    acc.x += bb.x; acc.y += bb.y; acc.z += bb.z; acc.w += bb.w;
    acc.x = acc.x > 0.f ? acc.x : expm1f(acc.x);
    acc.y = acc.y > 0.f ? acc.y : expm1f(acc.y);
    acc.z = acc.z > 0.f ? acc.z : expm1f(acc.z);
    acc.w = acc.w > 0.f ? acc.w : expm1f(acc.w);
    reinterpret_cast<float4*>(out)[(size_t)row * 32 + lane] = acc;
}

extern "C" void kernel_launch(void* const* d_in, const int* in_sizes, int n_in,
                              void* d_out, int out_size) {
    const int*   ei     = (const int*)d_in[1];
    const float* px     = (const float*)d_in[2];
    const int*   pei    = (const int*)d_in[3];
    const int*   unpool = (const int*)d_in[4];
    const float* W0 = (const float*)d_in[5];
    const float* b0 = (const float*)d_in[6];
    const float* W1 = (const float*)d_in[7];
    const float* b1 = (const float*)d_in[8];
    const float* W2 = (const float*)d_in[9];
    const float* b2 = (const float*)d_in[10];

    const int nf = in_sizes[0] / D;
    const int Ef = in_sizes[1] / 2;
    const int np = in_sizes[2] / D;
    const int Ep = in_sizes[3] / 2;
    float* out = (float*)d_out;

    float *buf1, *buf2, *dinvf, *dinvp;
    int *cntf, *rpf, *curf, *esrcf, *cntp, *rpp, *curp, *esrcp, *bsf, *bsp, *inv;
    unsigned char* wimg;
    cudaGetSymbolAddress((void**)&buf1,  g_buf1);
    cudaGetSymbolAddress((void**)&buf2,  g_buf2);
    cudaGetSymbolAddress((void**)&cntf,  g_cntf);
    cudaGetSymbolAddress((void**)&rpf,   g_rpf);
    cudaGetSymbolAddress((void**)&curf,  g_curf);
    cudaGetSymbolAddress((void**)&esrcf, g_esrcf);
    cudaGetSymbolAddress((void**)&dinvf, g_dinvf);
    cudaGetSymbolAddress((void**)&cntp,  g_cntp);
    cudaGetSymbolAddress((void**)&rpp,   g_rpp);
    cudaGetSymbolAddress((void**)&curp,  g_curp);
    cudaGetSymbolAddress((void**)&esrcp, g_esrcp);
    cudaGetSymbolAddress((void**)&dinvp, g_dinvp);
    cudaGetSymbolAddress((void**)&inv,   g_inv);
    cudaGetSymbolAddress((void**)&bsf,   g_bsf);
    cudaGetSymbolAddress((void**)&bsp,   g_bsp);
    cudaGetSymbolAddress((void**)&wimg,  g_wimg);

    const int GEMM_SMEM = 4 * 32768;
    cudaFuncSetAttribute(k_gemm_mma, cudaFuncAttributeMaxDynamicSharedMemorySize, GEMM_SMEM);

    const unsigned char* img0h = wimg;
    const unsigned char* img0l = wimg + 32768;
    const unsigned char* img1h = wimg + 2 * 32768;
    const unsigned char* img1l = wimg + 3 * 32768;
    const unsigned char* img2h = wimg + 4 * 32768;
    const unsigned char* img2l = wimg + 5 * 32768;

    const int nbf = cdiv(nf, 1024), nbp = cdiv(np, 1024);

    static cudaStream_t s1 = nullptr, s2 = nullptr;
    static cudaEvent_t ev_fork = nullptr, ev_g0 = nullptr, ev_csr = nullptr;
    if (!s1) {
        cudaStreamCreateWithFlags(&s1, cudaStreamNonBlocking);
        cudaStreamCreateWithFlags(&s2, cudaStreamNonBlocking);
        cudaEventCreateWithFlags(&ev_fork, cudaEventDisableTiming);
        cudaEventCreateWithFlags(&ev_g0, cudaEventDisableTiming);
        cudaEventCreateWithFlags(&ev_csr, cudaEventDisableTiming);
    }

    // ---- prologue (main stream) ----
    k_zero_prep<<<cdiv(nf, 256), 256>>>(cntf, cntp, inv, nf, np, W0, W1, W2);
    cudaEventRecord(ev_fork, 0);

    // s1: inv index + GEMM0 (px @ W0)
    cudaStreamWaitEvent(s1, ev_fork, 0);
    k_inv<<<cdiv(np, 256), 256, 0, s1>>>(unpool, inv, np);
    k_gemm_mma<<<cdiv(np, 128), 256, GEMM_SMEM, s1>>>(px, img0h, img0l, buf1, np);
    cudaEventRecord(ev_g0, s1);

    // s2: full-graph CSR (needed only at gather1)
    cudaStreamWaitEvent(s2, ev_fork, 0);
    k_hist<<<cdiv(Ef, 256), 256, 0, s2>>>(ei + Ef, Ef, cntf);
    k_bsum<<<nbf, 256, 0, s2>>>(cntf, nf, bsf);
    k_scanbs<<<1, 64, 0, s2>>>(bsf, nbf, rpf, nf);
    k_write<<<nbf, 256, 0, s2>>>(cntf, nf, bsf, rpf, curf, dinvf);
    k_place<<<cdiv(Ef, 256), 256, 0, s2>>>(ei, ei + Ef, Ef, curf, esrcf);
    cudaEventRecord(ev_csr, s2);

    // main: pooled CSR (short)
    k_hist<<<cdiv(Ep, 256), 256>>>(pei + Ep, Ep, cntp);
    k_bsum<<<nbp, 256>>>(cntp, np, bsp);
    k_scanbs<<<1, 64>>>(bsp, nbp, rpp, np);
    k_write<<<nbp, 256>>>(cntp, np, bsp, rpp, curp, dinvp);
    k_place<<<cdiv(Ep, 256), 256>>>(pei, pei + Ep, Ep, curp, esrcp);

    // conv0 gather (needs GEMM0)
    cudaStreamWaitEvent(0, ev_g0, 0);
    k_gather<<<cdiv(np, 8), 256>>>(rpp, esrcp, dinvp, buf1, b0, nullptr, buf2, np);

    // conv1: compact GEMM, then full-graph sparse gather (needs full CSR)
    k_gemm_mma<<<cdiv(np, 128), 256, GEMM_SMEM>>>(buf2, img1h, img1l, buf1, np);
    cudaStreamWaitEvent(0, ev_csr, 0);
    k_gather<<<cdiv(nf, 8), 256>>>(rpf, esrcf, dinvf, buf1, b1, inv, buf2, nf);

    // conv2: full GEMM + gather -> out
    k_gemm_mma<<<cdiv(nf, 128), 256, GEMM_SMEM>>>(buf2, img2h, img2l, buf1, nf);
    k_gather<<<cdiv(nf, 8), 256>>>(rpf, esrcf, dinvf, buf1, b2, nullptr, out, nf);
}